// round 11
// baseline (speedup 1.0000x reference)
#include <cuda_runtime.h>
#include <cuda_bf16.h>
#include <math.h>
#include <stdint.h>

#define BATCH 256
#define SEQ   512
#define DIM   512

static const long NEL = (long)BATCH * SEQ * DIM;  // 67108864

// ---------------------------------------------------------------------------
// Scratch: __device__ globals (allocation-free rule)
// ---------------------------------------------------------------------------
static __device__ __nv_bfloat16 g_xh[67108864], g_xl[67108864];   // X / later h
static __device__ __nv_bfloat16 g_xth[67108864], g_xtl[67108864]; // X^T (block 1)
static __device__ __nv_bfloat16 g_qh[67108864], g_ql[67108864];   // q1 / q2
static __device__ __nv_bfloat16 g_sh[67108864], g_sl[67108864];   // P hi/lo
static __device__ __nv_bfloat16 g_mh[67108864], g_ml[67108864];   // mix1
static __device__ float g_sf[67108864];                           // scores fp32
static __device__ __nv_bfloat16 g_w1h[262144], g_w1l[262144];
static __device__ __nv_bfloat16 g_wo1h[524288], g_wo1l[524288];
static __device__ __nv_bfloat16 g_w2h[262144], g_w2l[262144];
static __device__ float g_pbar[131072], g_qbar[131072];

// ---------------------------------------------------------------------------
// PTX helpers (sm_80+ baseline: cp.async / ldmatrix / mma.sync bf16)
// ---------------------------------------------------------------------------
__device__ __forceinline__ void cp_async16(uint32_t s, const void* g) {
    asm volatile("cp.async.cg.shared.global [%0], [%1], 16;"
                 :: "r"(s), "l"(__cvta_generic_to_global(g)) : "memory");
}

__device__ __forceinline__ void ldsm_x4(uint32_t addr, uint32_t& r0, uint32_t& r1,
                                        uint32_t& r2, uint32_t& r3) {
    asm volatile("ldmatrix.sync.aligned.m8n8.x4.shared.b16 {%0,%1,%2,%3}, [%4];"
                 : "=r"(r0), "=r"(r1), "=r"(r2), "=r"(r3) : "r"(addr));
}

__device__ __forceinline__ void mma16816(float* c, const uint32_t* a, const uint32_t* b) {
    asm volatile("mma.sync.aligned.m16n8k16.row.col.f32.bf16.bf16.f32 "
                 "{%0,%1,%2,%3}, {%4,%5,%6,%7}, {%8,%9}, {%0,%1,%2,%3};"
                 : "+f"(c[0]), "+f"(c[1]), "+f"(c[2]), "+f"(c[3])
                 : "r"(a[0]), "r"(a[1]), "r"(a[2]), "r"(a[3]), "r"(b[0]), "r"(b[1]));
}

// ---------------------------------------------------------------------------
// Split-bf16 HMMA GEMM.
//   C[m,n] = sum_k A[m,k]*B[n,k], A=aH+aL, B=bH+bL; AH*BH + AH*BL + AL*BH.
//   Block tile 128x128, BK=32, 256 thr (2x4 warps, 64x32 warp tile).
//   SMEM rows 128B = [hi 64B | lo 64B], XOR swizzle. 3-stage cp.async
//   pipeline (wait_group 1), one __syncthreads per chunk.
//   MMA issue order: product-outer (consecutive MMAs hit different
//   accumulators -> no HMMA RAW stalls).
// ---------------------------------------------------------------------------
#define BK      32
#define TILE_B  (128 * 128)           // 16384 B: one operand (hi+lo packed)
#define STAGE_B (2 * TILE_B)          // A, B
#define NSTAGE  3
#define GEMM_DYN_SMEM (NSTAGE * STAGE_B)   // 98304 B

// granule g (16B) at row r -> g ^ (r&7) within the 128B row
__device__ __forceinline__ void load_chunk(uint32_t sbase,
    const __nv_bfloat16* pAH, const __nv_bfloat16* pAL,
    const __nv_bfloat16* pBH, const __nv_bfloat16* pBL,
    long rowA, long colB, int lda, int ldb, int k0, int tid)
{
#pragma unroll
    for (int i = 0; i < 8; ++i) {
        int seg = tid + i * 256;            // 0..2047 16B segments
        int t   = seg >> 10;                // 0=A, 1=B
        int r   = (seg >> 3) & 127;         // row 0..127
        int g   = seg & 7;                  // granule 0..7 (0-3 hi, 4-7 lo)
        int c16 = g & 3;
        const __nv_bfloat16* src =
            (t ? ((g & 4) ? pBL : pBH) : ((g & 4) ? pAL : pAH));
        long row0 = t ? colB : rowA;
        int  ld   = t ? ldb  : lda;
        cp_async16(sbase + (uint32_t)(t * TILE_B + r * 128 + ((g ^ (r & 7)) * 16)),
                   src + (row0 + r) * (long)ld + k0 + c16 * 8);
    }
    asm volatile("cp.async.commit_group;" ::: "memory");
}

template<bool DUAL, bool TANH, bool OUTF32>
__global__ void __launch_bounds__(256, 2)
gemm_hmma(const __nv_bfloat16* __restrict__ aH, const __nv_bfloat16* __restrict__ aL,
          int lda, long sA,
          const __nv_bfloat16* __restrict__ bH, const __nv_bfloat16* __restrict__ bL,
          int ldb, long sB,
          const __nv_bfloat16* __restrict__ a2H, const __nv_bfloat16* __restrict__ a2L,
          const __nv_bfloat16* __restrict__ b2H, const __nv_bfloat16* __restrict__ b2L,
          __nv_bfloat16* __restrict__ cH, __nv_bfloat16* __restrict__ cL,
          float* __restrict__ cF,
          int ldc, long sC, int K)
{
    extern __shared__ char smem_raw[];
    const uint32_t smem = (uint32_t)__cvta_generic_to_shared(smem_raw);

    const int tid  = threadIdx.x;
    const int lane = tid & 31;
    const int wid  = tid >> 5;
    const int wm   = wid & 1;       // 2 m-groups of 64
    const int wn   = wid >> 1;      // 4 n-groups of 32
    const int bz   = blockIdx.z;
    const long rowA = (long)blockIdx.y * 128;
    const long colB = (long)blockIdx.x * 128;

    float acc[4][4][4];
#pragma unroll
    for (int i = 0; i < 4; ++i)
#pragma unroll
        for (int j = 0; j < 4; ++j)
#pragma unroll
            for (int k = 0; k < 4; ++k) acc[i][j][k] = 0.f;

    const int npc    = K / BK;                 // chunks per pair
    const int nchunk = (DUAL ? 2 : 1) * npc;

    const __nv_bfloat16* AH0 = aH + bz * sA;
    const __nv_bfloat16* AL0 = aL + bz * sA;
    const __nv_bfloat16* BH0 = bH + bz * sB;
    const __nv_bfloat16* BL0 = bL + bz * sB;
    const __nv_bfloat16* AH1 = DUAL ? a2H + bz * sA : nullptr;
    const __nv_bfloat16* AL1 = DUAL ? a2L + bz * sA : nullptr;
    const __nv_bfloat16* BH1 = DUAL ? b2H + bz * sB : nullptr;
    const __nv_bfloat16* BL1 = DUAL ? b2L + bz * sB : nullptr;

    // Per-thread fragment address constants (swizzle folded in; row&7 == lane&7).
    const uint32_t aRowB = (uint32_t)((wm * 64 + (lane & 15)) * 128);
    const uint32_t bRowB = (uint32_t)((wn * 32 + ((lane >> 4) << 3) + (lane & 7)) * 128);
    uint32_t gA16[2], gB16[2];
#pragma unroll
    for (int ks = 0; ks < 2; ++ks) {
        gA16[ks] = (uint32_t)(((ks * 2 + (lane >> 4)) ^ (lane & 7)) * 16);
        gB16[ks] = (uint32_t)(((ks * 2 + ((lane >> 3) & 1)) ^ (lane & 7)) * 16);
    }

    // prologue: chunks 0,1 -> stages 0,1 (all GEMMs here have nchunk >= 16)
    load_chunk(smem,           AH0, AL0, BH0, BL0, rowA, colB, lda, ldb, 0,  tid);
    load_chunk(smem + STAGE_B, AH0, AL0, BH0, BL0, rowA, colB, lda, ldb, BK, tid);

    for (int c = 0; c < nchunk; ++c) {
        if (c + 1 < nchunk)
            asm volatile("cp.async.wait_group 1;" ::: "memory");
        else
            asm volatile("cp.async.wait_group 0;" ::: "memory");
        __syncthreads();   // stage c%3 ready; all warps done with stage (c-1)%3

        if (c + 2 < nchunk) {
            int cn = c + 2;
            int p  = cn / npc;
            int k0 = (cn % npc) * BK;
            uint32_t dst = smem + (uint32_t)((cn % NSTAGE) * STAGE_B);
            if (!DUAL || p == 0)
                load_chunk(dst, AH0, AL0, BH0, BL0, rowA, colB, lda, ldb, k0, tid);
            else
                load_chunk(dst, AH1, AL1, BH1, BL1, rowA, colB, lda, ldb, k0, tid);
        }

        const uint32_t sA_ = smem + (uint32_t)((c % NSTAGE) * STAGE_B);
        const uint32_t sB_ = sA_ + TILE_B;

#pragma unroll
        for (int ks = 0; ks < 2; ++ks) {
            uint32_t bhf[4][2], blf[4][2];
#pragma unroll
            for (int np = 0; np < 2; ++np) {
                uint32_t boff = bRowB + (uint32_t)(np * 16 * 128);
                ldsm_x4(sB_ + boff + gB16[ks], bhf[2 * np][0], bhf[2 * np][1],
                                               bhf[2 * np + 1][0], bhf[2 * np + 1][1]);
                ldsm_x4(sB_ + (boff + gB16[ks] ^ 64u), blf[2 * np][0], blf[2 * np][1],
                                               blf[2 * np + 1][0], blf[2 * np + 1][1]);
            }
#pragma unroll
            for (int mf = 0; mf < 4; ++mf) {
                uint32_t aoff = aRowB + (uint32_t)(mf * 16 * 128);
                uint32_t ahf[4], alf[4];
                ldsm_x4(sA_ + aoff + gA16[ks], ahf[0], ahf[1], ahf[2], ahf[3]);
                ldsm_x4(sA_ + (aoff + gA16[ks] ^ 64u), alf[0], alf[1], alf[2], alf[3]);
                // product-outer: consecutive MMAs write DIFFERENT accumulators
                // (same-acc reuse distance = 4 issues >= HMMA latency).
                // Per-accumulator order stays hh -> hl -> lh (bit-identical).
#pragma unroll
                for (int nf = 0; nf < 4; ++nf)
                    mma16816(acc[mf][nf], ahf, bhf[nf]);  // hi*hi
#pragma unroll
                for (int nf = 0; nf < 4; ++nf)
                    mma16816(acc[mf][nf], ahf, blf[nf]);  // hi*lo
#pragma unroll
                for (int nf = 0; nf < 4; ++nf)
                    mma16816(acc[mf][nf], alf, bhf[nf]);  // lo*hi
            }
        }
    }

    // Epilogue: c0,c1 -> (row=rq, col=cq..cq+1); c2,c3 -> row+8.
    const int rq = lane >> 2, cq = (lane & 3) * 2;

#pragma unroll
    for (int mf = 0; mf < 4; ++mf) {
#pragma unroll
        for (int nf = 0; nf < 4; ++nf) {
            long col = colB + wn * 32 + nf * 8 + cq;
#pragma unroll
            for (int half = 0; half < 2; ++half) {
                long row = rowA + wm * 64 + mf * 16 + rq + half * 8;
                float v0 = acc[mf][nf][half * 2 + 0];
                float v1 = acc[mf][nf][half * 2 + 1];
                if (OUTF32) {
                    float* CF = cF + (long)bz * sC;
                    *(float2*)(CF + row * (long)ldc + col) = make_float2(v0, v1);
                } else {
                    if (TANH) { v0 = tanhf(v0); v1 = tanhf(v1); }
                    __nv_bfloat16 h0 = __float2bfloat16_rn(v0);
                    __nv_bfloat16 h1 = __float2bfloat16_rn(v1);
                    __nv_bfloat16 l0 = __float2bfloat16_rn(v0 - __bfloat162float(h0));
                    __nv_bfloat16 l1 = __float2bfloat16_rn(v1 - __bfloat162float(h1));
                    __nv_bfloat162 hp; hp.x = h0; hp.y = h1;
                    __nv_bfloat162 lp; lp.x = l0; lp.y = l1;
                    __nv_bfloat16* CH = cH + (long)bz * sC;
                    __nv_bfloat16* CL = cL + (long)bz * sC;
                    *(__nv_bfloat162*)(CH + row * (long)ldc + col) = hp;
                    *(__nv_bfloat162*)(CL + row * (long)ldc + col) = lp;
                }
            }
        }
    }
}

// ---------------------------------------------------------------------------
// fp32 -> (hi, lo) bf16 split helpers
// ---------------------------------------------------------------------------
__device__ __forceinline__ void split4(float4 v, uint2& uh, uint2& ul)
{
    float f[4] = {v.x, v.y, v.z, v.w};
    __nv_bfloat16 h[4], l[4];
#pragma unroll
    for (int j = 0; j < 4; ++j) {
        h[j] = __float2bfloat16_rn(f[j]);
        l[j] = __float2bfloat16_rn(f[j] - __bfloat162float(h[j]));
    }
    __nv_bfloat162 h01, h23, l01, l23;
    h01.x = h[0]; h01.y = h[1]; h23.x = h[2]; h23.y = h[3];
    l01.x = l[0]; l01.y = l[1]; l23.x = l[2]; l23.y = l[3];
    uh.x = *(uint32_t*)&h01; uh.y = *(uint32_t*)&h23;
    ul.x = *(uint32_t*)&l01; ul.y = *(uint32_t*)&l23;
}

__device__ __forceinline__ void split1(float f, __nv_bfloat16& h, __nv_bfloat16& l)
{
    h = __float2bfloat16_rn(f);
    l = __float2bfloat16_rn(f - __bfloat162float(h));
}

// Fused weight split: W1 (65536 f4) | Wout1 (131072 f4) | W2 (65536 f4)
__global__ void __launch_bounds__(256)
wsplit_kernel(const float4* __restrict__ w1, const float4* __restrict__ wo1,
              const float4* __restrict__ w2,
              uint2* __restrict__ w1h, uint2* __restrict__ w1l,
              uint2* __restrict__ wo1h, uint2* __restrict__ wo1l,
              uint2* __restrict__ w2h, uint2* __restrict__ w2l)
{
    long i = (long)blockIdx.x * blockDim.x + threadIdx.x;
    const float4* src; uint2 *dh, *dl; long j;
    if (i < 65536)       { src = w1;  dh = w1h;  dl = w1l;  j = i; }
    else if (i < 196608) { src = wo1; dh = wo1h; dl = wo1l; j = i - 65536; }
    else                 { src = w2;  dh = w2h;  dl = w2l;  j = i - 196608; }
    uint2 uh, ul;
    split4(src[j], uh, ul);
    dh[j] = uh; dl[j] = ul;
}

// ---------------------------------------------------------------------------
// Fused X split + transpose: reads X fp32 once, writes xh/xl (row-major) and
// xth/xtl (transposed). 32x32 tiles, block (32,8), grid (16,16,256).
// ---------------------------------------------------------------------------
__global__ void __launch_bounds__(256)
splitT_kernel(const float* __restrict__ X,
              __nv_bfloat16* __restrict__ xh, __nv_bfloat16* __restrict__ xl,
              __nv_bfloat16* __restrict__ xth, __nv_bfloat16* __restrict__ xtl)
{
    __shared__ float tile[32][33];
    const long base = (long)blockIdx.z * 262144;
    const int tx = threadIdx.x, ty = threadIdx.y;
    const int x = blockIdx.x * 32 + tx;
    const int y0 = blockIdx.y * 32;

#pragma unroll
    for (int j = 0; j < 32; j += 8) {
        long idx = base + (long)(y0 + ty + j) * 512 + x;
        float v = X[idx];
        tile[ty + j][tx] = v;
        __nv_bfloat16 h, l;
        split1(v, h, l);
        xh[idx] = h; xl[idx] = l;
    }
    __syncthreads();

    const int xo = blockIdx.y * 32 + tx;
    const int yo0 = blockIdx.x * 32;
#pragma unroll
    for (int j = 0; j < 32; j += 8) {
        long idx = base + (long)(yo0 + ty + j) * 512 + xo;
        float v = tile[tx][ty + j];
        __nv_bfloat16 h, l;
        split1(v, h, l);
        xth[idx] = h; xtl[idx] = l;
    }
}

// ---------------------------------------------------------------------------
// Row softmax over 512: fp32 in, hi/lo bf16 out. 128 thr/row.
// ---------------------------------------------------------------------------
__global__ void __launch_bounds__(128)
softmax512_f32(const float* __restrict__ S,
               __nv_bfloat16* __restrict__ PH, __nv_bfloat16* __restrict__ PL)
{
    __shared__ float redm[4], reds[4];
    const long row = blockIdx.x;
    const int t = threadIdx.x;

    float4 vv = ((const float4*)(S + row * 512))[t];
    float v[4] = {vv.x, vv.y, vv.z, vv.w};

    float m = fmaxf(fmaxf(v[0], v[1]), fmaxf(v[2], v[3]));
#pragma unroll
    for (int o = 16; o; o >>= 1) m = fmaxf(m, __shfl_xor_sync(0xffffffffu, m, o));
    if ((t & 31) == 0) redm[t >> 5] = m;
    __syncthreads();
    m = fmaxf(fmaxf(redm[0], redm[1]), fmaxf(redm[2], redm[3]));

    float s = 0.f;
#pragma unroll
    for (int j = 0; j < 4; ++j) { v[j] = __expf(v[j] - m); s += v[j]; }
#pragma unroll
    for (int o = 16; o; o >>= 1) s += __shfl_xor_sync(0xffffffffu, s, o);
    if ((t & 31) == 0) reds[t >> 5] = s;
    __syncthreads();
    s = reds[0] + reds[1] + reds[2] + reds[3];
    float r = 1.0f / s;

    float4 w = make_float4(v[0] * r, v[1] * r, v[2] * r, v[3] * r);
    uint2 uh, ul;
    split4(w, uh, ul);
    ((uint2*)(PH + row * 512))[t] = uh;
    ((uint2*)(PL + row * 512))[t] = ul;
}

// ---------------------------------------------------------------------------
// Fused column means: z<256 -> pbar from (sh,sl); z>=256 -> qbar from (qh,ql).
// out[b,j] = (1/512) * sum_i (hi+lo)[b,i,j]
// ---------------------------------------------------------------------------
__global__ void __launch_bounds__(512)
meanPQ_kernel(const __nv_bfloat16* __restrict__ ph, const __nv_bfloat16* __restrict__ pl,
              const __nv_bfloat16* __restrict__ qh, const __nv_bfloat16* __restrict__ ql,
              float* __restrict__ pbar, float* __restrict__ qbar)
{
    const int z = blockIdx.x;
    const bool isq = z >= 256;
    const __nv_bfloat16* hi = isq ? qh : ph;
    const __nv_bfloat16* lo = isq ? ql : pl;
    float* out = isq ? qbar : pbar;
    const int b = z & 255;
    const long base = (long)b * 262144 + threadIdx.x;
    float s = 0.f;
#pragma unroll 4
    for (int i = 0; i < 512; ++i) {
        long off = base + (long)i * 512;
        s += __bfloat162float(hi[off]) + __bfloat162float(lo[off]);
    }
    out[b * 512 + threadIdx.x] = s * (1.0f / 512.0f);
}

// ---------------------------------------------------------------------------
// Fused mixbar + final projection. One block per batch b (512 thr):
//   mb[d] = sum_m pbar[b,m] * (hh+hl)[b,m,d]        (into smem)
//   out[b,d] = sum_c mb[c]*W[d,c] + sum_c qbar[b,c]*W[d,512+c]
// ---------------------------------------------------------------------------
__global__ void __launch_bounds__(512)
mixfinal_kernel(const float* __restrict__ pbar, const float* __restrict__ qbar,
                const __nv_bfloat16* __restrict__ hh, const __nv_bfloat16* __restrict__ hl,
                const float* __restrict__ W, float* __restrict__ out)
{
    __shared__ float pb[512], mb[512], qb[512];
    const int b = blockIdx.x, d = threadIdx.x;
    pb[d] = pbar[b * 512 + d];
    qb[d] = qbar[b * 512 + d];
    __syncthreads();

    const long base = (long)b * 262144 + d;
    float s = 0.f;
#pragma unroll 4
    for (int m = 0; m < 512; ++m) {
        long off = base + (long)m * 512;
        s += pb[m] * (__bfloat162float(hh[off]) + __bfloat162float(hl[off]));
    }
    mb[d] = s;
    __syncthreads();

    const float4* w4 = (const float4*)(W + (long)d * 1024);
    float o = 0.f;
#pragma unroll 4
    for (int c4 = 0; c4 < 128; ++c4) {
        float4 w = w4[c4];
        int c = c4 * 4;
        o += mb[c] * w.x + mb[c + 1] * w.y + mb[c + 2] * w.z + mb[c + 3] * w.w;
    }
#pragma unroll 4
    for (int c4 = 128; c4 < 256; ++c4) {
        float4 w = w4[c4];
        int c = c4 * 4 - 512;
        o += qb[c] * w.x + qb[c + 1] * w.y + qb[c + 2] * w.z + qb[c + 3] * w.w;
    }
    out[b * 512 + d] = o;
}

// ---------------------------------------------------------------------------

extern "C" void kernel_launch(void* const* d_in, const int* in_sizes, int n_in,
                              void* d_out, int out_size)
{
    const float* x     = (const float*)d_in[0];
    const float* Win1  = (const float*)d_in[1];
    const float* Wout1 = (const float*)d_in[2];
    const float* Win2  = (const float*)d_in[3];
    const float* Wout2 = (const float*)d_in[4];
    float* out = (float*)d_out;

    __nv_bfloat16 *xh, *xl, *xth, *xtl, *qh, *ql, *sh, *sl, *mh, *ml;
    __nv_bfloat16 *w1h, *w1l, *wo1h, *wo1l, *w2h, *w2l;
    float *sf, *pbar, *qbar;
    cudaGetSymbolAddress((void**)&xh,  g_xh);   cudaGetSymbolAddress((void**)&xl,  g_xl);
    cudaGetSymbolAddress((void**)&xth, g_xth);  cudaGetSymbolAddress((void**)&xtl, g_xtl);
    cudaGetSymbolAddress((void**)&qh,  g_qh);   cudaGetSymbolAddress((void**)&ql,  g_ql);
    cudaGetSymbolAddress((void**)&sh,  g_sh);   cudaGetSymbolAddress((void**)&sl,  g_sl);
    cudaGetSymbolAddress((void**)&mh,  g_mh);   cudaGetSymbolAddress((void**)&ml,  g_ml);
    cudaGetSymbolAddress((void**)&sf,  g_sf);
    cudaGetSymbolAddress((void**)&w1h, g_w1h);  cudaGetSymbolAddress((void**)&w1l, g_w1l);
    cudaGetSymbolAddress((void**)&wo1h,g_wo1h); cudaGetSymbolAddress((void**)&wo1l,g_wo1l);
    cudaGetSymbolAddress((void**)&w2h, g_w2h);  cudaGetSymbolAddress((void**)&w2l, g_w2l);
    cudaGetSymbolAddress((void**)&pbar, g_pbar);
    cudaGetSymbolAddress((void**)&qbar, g_qbar);

    cudaFuncSetAttribute(gemm_hmma<false, false, false>,
                         cudaFuncAttributeMaxDynamicSharedMemorySize, GEMM_DYN_SMEM);
    cudaFuncSetAttribute(gemm_hmma<false, false, true>,
                         cudaFuncAttributeMaxDynamicSharedMemorySize, GEMM_DYN_SMEM);
    cudaFuncSetAttribute(gemm_hmma<true, true, false>,
                         cudaFuncAttributeMaxDynamicSharedMemorySize, GEMM_DYN_SMEM);

    const int  M_FLAT = BATCH * SEQ;     // 131072
    const long LDb = 262144;

    // ---- splits (X split fused with transpose) ----
    wsplit_kernel<<<262144 / 256, 256>>>(
        (const float4*)Win1, (const float4*)Wout1, (const float4*)Win2,
        (uint2*)w1h, (uint2*)w1l, (uint2*)wo1h, (uint2*)wo1l, (uint2*)w2h, (uint2*)w2l);
    splitT_kernel<<<dim3(16, 16, 256), dim3(32, 8)>>>(x, xh, xl, xth, xtl);

    // ---- block 1 ----
    // q1 = X @ Win1^T
    gemm_hmma<false, false, false><<<dim3(4, 1024, 1), 256, GEMM_DYN_SMEM>>>(
        xh, xl, 512, 0, w1h, w1l, 512, 0,
        nullptr, nullptr, nullptr, nullptr, qh, ql, nullptr, 512, 0, 512);
    // S1[b] = q1[b] @ X[b]^T  (fp32 out)
    gemm_hmma<false, false, true><<<dim3(4, 4, 256), 256, GEMM_DYN_SMEM>>>(
        qh, ql, 512, LDb, xh, xl, 512, LDb,
        nullptr, nullptr, nullptr, nullptr, nullptr, nullptr, sf, 512, LDb, 512);
    softmax512_f32<<<M_FLAT, 128>>>(sf, sh, sl);
    // mix1[b] = P1[b] @ X[b]   (B = X^T, K-major over m)
    gemm_hmma<false, false, false><<<dim3(4, 4, 256), 256, GEMM_DYN_SMEM>>>(
        sh, sl, 512, LDb, xth, xtl, 512, LDb,
        nullptr, nullptr, nullptr, nullptr, mh, ml, nullptr, 512, LDb, 512);
    // h = tanh(mix1 @ Wout1[:, :512]^T + q1 @ Wout1[:, 512:]^T) -> overwrite X slots
    gemm_hmma<true, true, false><<<dim3(4, 1024, 1), 256, GEMM_DYN_SMEM>>>(
        mh, ml, 512, 0, wo1h, wo1l, 1024, 0,
        qh, ql, wo1h + 512, wo1l + 512, xh, xl, nullptr, 512, 0, 512);

    // ---- block 2 (pooling collapsed: no mix2 / out-proj GEMMs) ----
    // q2 = h @ Win2^T
    gemm_hmma<false, false, false><<<dim3(4, 1024, 1), 256, GEMM_DYN_SMEM>>>(
        xh, xl, 512, 0, w2h, w2l, 512, 0,
        nullptr, nullptr, nullptr, nullptr, qh, ql, nullptr, 512, 0, 512);
    // S2[b] = q2[b] @ h[b]^T  (fp32 out)
    gemm_hmma<false, false, true><<<dim3(4, 4, 256), 256, GEMM_DYN_SMEM>>>(
        qh, ql, 512, LDb, xh, xl, 512, LDb,
        nullptr, nullptr, nullptr, nullptr, nullptr, nullptr, sf, 512, LDb, 512);
    softmax512_f32<<<M_FLAT, 128>>>(sf, sh, sl);

    // ---- fused tail ----
    meanPQ_kernel<<<512, 512>>>(sh, sl, qh, ql, pbar, qbar);
    mixfinal_kernel<<<BATCH, 512>>>(pbar, qbar, xh, xl, Wout2, out);
}

// round 12
// speedup vs baseline: 1.0007x; 1.0007x over previous
#include <cuda_runtime.h>
#include <cuda_bf16.h>
#include <math.h>
#include <stdint.h>

#define BATCH 256
#define SEQ   512
#define DIM   512

static const long NEL = (long)BATCH * SEQ * DIM;  // 67108864

// ---------------------------------------------------------------------------
// Scratch: __device__ globals (allocation-free rule)
// ---------------------------------------------------------------------------
static __device__ __nv_bfloat16 g_xh[67108864], g_xl[67108864];   // X / later h
static __device__ __nv_bfloat16 g_xth[67108864], g_xtl[67108864]; // X^T (block 1)
static __device__ __nv_bfloat16 g_qh[67108864], g_ql[67108864];   // q1 / q2
static __device__ __nv_bfloat16 g_sh[67108864], g_sl[67108864];   // P hi/lo
static __device__ __nv_bfloat16 g_mh[67108864], g_ml[67108864];   // mix1
static __device__ float g_sf[67108864];                           // scores fp32
static __device__ __nv_bfloat16 g_w1h[262144], g_w1l[262144];
static __device__ __nv_bfloat16 g_wo1h[524288], g_wo1l[524288];
static __device__ __nv_bfloat16 g_w2h[262144], g_w2l[262144];
static __device__ float g_pbar[131072], g_qbar[131072];

// ---------------------------------------------------------------------------
// PTX helpers (sm_80+ baseline: cp.async / ldmatrix / mma.sync bf16)
// ---------------------------------------------------------------------------
__device__ __forceinline__ void cp_async16(uint32_t s, const void* g) {
    asm volatile("cp.async.cg.shared.global [%0], [%1], 16;"
                 :: "r"(s), "l"(__cvta_generic_to_global(g)) : "memory");
}

__device__ __forceinline__ void ldsm_x4(uint32_t addr, uint32_t& r0, uint32_t& r1,
                                        uint32_t& r2, uint32_t& r3) {
    asm volatile("ldmatrix.sync.aligned.m8n8.x4.shared.b16 {%0,%1,%2,%3}, [%4];"
                 : "=r"(r0), "=r"(r1), "=r"(r2), "=r"(r3) : "r"(addr));
}

__device__ __forceinline__ void mma16816(float* c, const uint32_t* a, const uint32_t* b) {
    asm volatile("mma.sync.aligned.m16n8k16.row.col.f32.bf16.bf16.f32 "
                 "{%0,%1,%2,%3}, {%4,%5,%6,%7}, {%8,%9}, {%0,%1,%2,%3};"
                 : "+f"(c[0]), "+f"(c[1]), "+f"(c[2]), "+f"(c[3])
                 : "r"(a[0]), "r"(a[1]), "r"(a[2]), "r"(a[3]), "r"(b[0]), "r"(b[1]));
}

// ---------------------------------------------------------------------------
// Split-bf16 HMMA GEMM.
//   C[m,n] = sum_k A[m,k]*B[n,k], A=aH+aL, B=bH+bL; AH*BH + AH*BL + AL*BH.
//   Block tile 128x128, BK=32, 256 thr (2x4 warps, 64x32 warp tile).
//   SMEM rows 128B = [hi 64B | lo 64B], XOR swizzle. 3-stage cp.async
//   pipeline (wait_group 1), one __syncthreads per chunk.
//   MMA issue order: product-outer (consecutive MMAs hit different
//   accumulators -> no HMMA RAW stalls).
// ---------------------------------------------------------------------------
#define BK      32
#define TILE_B  (128 * 128)           // 16384 B: one operand (hi+lo packed)
#define STAGE_B (2 * TILE_B)          // A, B
#define NSTAGE  3
#define GEMM_DYN_SMEM (NSTAGE * STAGE_B)   // 98304 B

// granule g (16B) at row r -> g ^ (r&7) within the 128B row
__device__ __forceinline__ void load_chunk(uint32_t sbase,
    const __nv_bfloat16* pAH, const __nv_bfloat16* pAL,
    const __nv_bfloat16* pBH, const __nv_bfloat16* pBL,
    long rowA, long colB, int lda, int ldb, int k0, int tid)
{
#pragma unroll
    for (int i = 0; i < 8; ++i) {
        int seg = tid + i * 256;            // 0..2047 16B segments
        int t   = seg >> 10;                // 0=A, 1=B
        int r   = (seg >> 3) & 127;         // row 0..127
        int g   = seg & 7;                  // granule 0..7 (0-3 hi, 4-7 lo)
        int c16 = g & 3;
        const __nv_bfloat16* src =
            (t ? ((g & 4) ? pBL : pBH) : ((g & 4) ? pAL : pAH));
        long row0 = t ? colB : rowA;
        int  ld   = t ? ldb  : lda;
        cp_async16(sbase + (uint32_t)(t * TILE_B + r * 128 + ((g ^ (r & 7)) * 16)),
                   src + (row0 + r) * (long)ld + k0 + c16 * 8);
    }
    asm volatile("cp.async.commit_group;" ::: "memory");
}

template<bool DUAL, bool TANH, bool OUTF32>
__global__ void __launch_bounds__(256, 2)
gemm_hmma(const __nv_bfloat16* __restrict__ aH, const __nv_bfloat16* __restrict__ aL,
          int lda, long sA,
          const __nv_bfloat16* __restrict__ bH, const __nv_bfloat16* __restrict__ bL,
          int ldb, long sB,
          const __nv_bfloat16* __restrict__ a2H, const __nv_bfloat16* __restrict__ a2L,
          const __nv_bfloat16* __restrict__ b2H, const __nv_bfloat16* __restrict__ b2L,
          __nv_bfloat16* __restrict__ cH, __nv_bfloat16* __restrict__ cL,
          float* __restrict__ cF,
          int ldc, long sC, int K)
{
    extern __shared__ char smem_raw[];
    const uint32_t smem = (uint32_t)__cvta_generic_to_shared(smem_raw);

    const int tid  = threadIdx.x;
    const int lane = tid & 31;
    const int wid  = tid >> 5;
    const int wm   = wid & 1;       // 2 m-groups of 64
    const int wn   = wid >> 1;      // 4 n-groups of 32
    const int bz   = blockIdx.z;
    const long rowA = (long)blockIdx.y * 128;
    const long colB = (long)blockIdx.x * 128;

    float acc[4][4][4];
#pragma unroll
    for (int i = 0; i < 4; ++i)
#pragma unroll
        for (int j = 0; j < 4; ++j)
#pragma unroll
            for (int k = 0; k < 4; ++k) acc[i][j][k] = 0.f;

    const int npc    = K / BK;                 // chunks per pair
    const int nchunk = (DUAL ? 2 : 1) * npc;

    const __nv_bfloat16* AH0 = aH + bz * sA;
    const __nv_bfloat16* AL0 = aL + bz * sA;
    const __nv_bfloat16* BH0 = bH + bz * sB;
    const __nv_bfloat16* BL0 = bL + bz * sB;
    const __nv_bfloat16* AH1 = DUAL ? a2H + bz * sA : nullptr;
    const __nv_bfloat16* AL1 = DUAL ? a2L + bz * sA : nullptr;
    const __nv_bfloat16* BH1 = DUAL ? b2H + bz * sB : nullptr;
    const __nv_bfloat16* BL1 = DUAL ? b2L + bz * sB : nullptr;

    // Per-thread fragment address constants (swizzle folded in; row&7 == lane&7).
    const uint32_t aRowB = (uint32_t)((wm * 64 + (lane & 15)) * 128);
    const uint32_t bRowB = (uint32_t)((wn * 32 + ((lane >> 4) << 3) + (lane & 7)) * 128);
    uint32_t gA16[2], gB16[2];
#pragma unroll
    for (int ks = 0; ks < 2; ++ks) {
        gA16[ks] = (uint32_t)(((ks * 2 + (lane >> 4)) ^ (lane & 7)) * 16);
        gB16[ks] = (uint32_t)(((ks * 2 + ((lane >> 3) & 1)) ^ (lane & 7)) * 16);
    }

    // prologue: chunks 0,1 -> stages 0,1 (all GEMMs here have nchunk >= 16)
    load_chunk(smem,           AH0, AL0, BH0, BL0, rowA, colB, lda, ldb, 0,  tid);
    load_chunk(smem + STAGE_B, AH0, AL0, BH0, BL0, rowA, colB, lda, ldb, BK, tid);

    for (int c = 0; c < nchunk; ++c) {
        if (c + 1 < nchunk)
            asm volatile("cp.async.wait_group 1;" ::: "memory");
        else
            asm volatile("cp.async.wait_group 0;" ::: "memory");
        __syncthreads();   // stage c%3 ready; all warps done with stage (c-1)%3

        if (c + 2 < nchunk) {
            int cn = c + 2;
            int p  = cn / npc;
            int k0 = (cn % npc) * BK;
            uint32_t dst = smem + (uint32_t)((cn % NSTAGE) * STAGE_B);
            if (!DUAL || p == 0)
                load_chunk(dst, AH0, AL0, BH0, BL0, rowA, colB, lda, ldb, k0, tid);
            else
                load_chunk(dst, AH1, AL1, BH1, BL1, rowA, colB, lda, ldb, k0, tid);
        }

        const uint32_t sA_ = smem + (uint32_t)((c % NSTAGE) * STAGE_B);
        const uint32_t sB_ = sA_ + TILE_B;

#pragma unroll
        for (int ks = 0; ks < 2; ++ks) {
            uint32_t bhf[4][2], blf[4][2];
#pragma unroll
            for (int np = 0; np < 2; ++np) {
                uint32_t boff = bRowB + (uint32_t)(np * 16 * 128);
                ldsm_x4(sB_ + boff + gB16[ks], bhf[2 * np][0], bhf[2 * np][1],
                                               bhf[2 * np + 1][0], bhf[2 * np + 1][1]);
                ldsm_x4(sB_ + (boff + gB16[ks] ^ 64u), blf[2 * np][0], blf[2 * np][1],
                                               blf[2 * np + 1][0], blf[2 * np + 1][1]);
            }
#pragma unroll
            for (int mf = 0; mf < 4; ++mf) {
                uint32_t aoff = aRowB + (uint32_t)(mf * 16 * 128);
                uint32_t ahf[4], alf[4];
                ldsm_x4(sA_ + aoff + gA16[ks], ahf[0], ahf[1], ahf[2], ahf[3]);
                ldsm_x4(sA_ + (aoff + gA16[ks] ^ 64u), alf[0], alf[1], alf[2], alf[3]);
                // product-outer: consecutive MMAs write DIFFERENT accumulators
                // (same-acc reuse distance = 4 issues >= HMMA latency).
                // Per-accumulator order stays hh -> hl -> lh (bit-identical).
#pragma unroll
                for (int nf = 0; nf < 4; ++nf)
                    mma16816(acc[mf][nf], ahf, bhf[nf]);  // hi*hi
#pragma unroll
                for (int nf = 0; nf < 4; ++nf)
                    mma16816(acc[mf][nf], ahf, blf[nf]);  // hi*lo
#pragma unroll
                for (int nf = 0; nf < 4; ++nf)
                    mma16816(acc[mf][nf], alf, bhf[nf]);  // lo*hi
            }
        }
    }

    // Epilogue: c0,c1 -> (row=rq, col=cq..cq+1); c2,c3 -> row+8.
    const int rq = lane >> 2, cq = (lane & 3) * 2;

#pragma unroll
    for (int mf = 0; mf < 4; ++mf) {
#pragma unroll
        for (int nf = 0; nf < 4; ++nf) {
            long col = colB + wn * 32 + nf * 8 + cq;
#pragma unroll
            for (int half = 0; half < 2; ++half) {
                long row = rowA + wm * 64 + mf * 16 + rq + half * 8;
                float v0 = acc[mf][nf][half * 2 + 0];
                float v1 = acc[mf][nf][half * 2 + 1];
                if (OUTF32) {
                    float* CF = cF + (long)bz * sC;
                    *(float2*)(CF + row * (long)ldc + col) = make_float2(v0, v1);
                } else {
                    if (TANH) { v0 = tanhf(v0); v1 = tanhf(v1); }
                    __nv_bfloat16 h0 = __float2bfloat16_rn(v0);
                    __nv_bfloat16 h1 = __float2bfloat16_rn(v1);
                    __nv_bfloat16 l0 = __float2bfloat16_rn(v0 - __bfloat162float(h0));
                    __nv_bfloat16 l1 = __float2bfloat16_rn(v1 - __bfloat162float(h1));
                    __nv_bfloat162 hp; hp.x = h0; hp.y = h1;
                    __nv_bfloat162 lp; lp.x = l0; lp.y = l1;
                    __nv_bfloat16* CH = cH + (long)bz * sC;
                    __nv_bfloat16* CL = cL + (long)bz * sC;
                    *(__nv_bfloat162*)(CH + row * (long)ldc + col) = hp;
                    *(__nv_bfloat162*)(CL + row * (long)ldc + col) = lp;
                }
            }
        }
    }
}

// ---------------------------------------------------------------------------
// fp32 -> (hi, lo) bf16 split helpers
// ---------------------------------------------------------------------------
__device__ __forceinline__ void split4(float4 v, uint2& uh, uint2& ul)
{
    float f[4] = {v.x, v.y, v.z, v.w};
    __nv_bfloat16 h[4], l[4];
#pragma unroll
    for (int j = 0; j < 4; ++j) {
        h[j] = __float2bfloat16_rn(f[j]);
        l[j] = __float2bfloat16_rn(f[j] - __bfloat162float(h[j]));
    }
    __nv_bfloat162 h01, h23, l01, l23;
    h01.x = h[0]; h01.y = h[1]; h23.x = h[2]; h23.y = h[3];
    l01.x = l[0]; l01.y = l[1]; l23.x = l[2]; l23.y = l[3];
    uh.x = *(uint32_t*)&h01; uh.y = *(uint32_t*)&h23;
    ul.x = *(uint32_t*)&l01; ul.y = *(uint32_t*)&l23;
}

__device__ __forceinline__ void split1(float f, __nv_bfloat16& h, __nv_bfloat16& l)
{
    h = __float2bfloat16_rn(f);
    l = __float2bfloat16_rn(f - __bfloat162float(h));
}

// Fused weight split: W1 (65536 f4) | Wout1 (131072 f4) | W2 (65536 f4)
__global__ void __launch_bounds__(256)
wsplit_kernel(const float4* __restrict__ w1, const float4* __restrict__ wo1,
              const float4* __restrict__ w2,
              uint2* __restrict__ w1h, uint2* __restrict__ w1l,
              uint2* __restrict__ wo1h, uint2* __restrict__ wo1l,
              uint2* __restrict__ w2h, uint2* __restrict__ w2l)
{
    long i = (long)blockIdx.x * blockDim.x + threadIdx.x;
    const float4* src; uint2 *dh, *dl; long j;
    if (i < 65536)       { src = w1;  dh = w1h;  dl = w1l;  j = i; }
    else if (i < 196608) { src = wo1; dh = wo1h; dl = wo1l; j = i - 65536; }
    else                 { src = w2;  dh = w2h;  dl = w2l;  j = i - 196608; }
    uint2 uh, ul;
    split4(src[j], uh, ul);
    dh[j] = uh; dl[j] = ul;
}

// ---------------------------------------------------------------------------
// Fused X split + transpose: reads X fp32 once, writes xh/xl (row-major) and
// xth/xtl (transposed). 32x32 tiles, block (32,8), grid (16,16,256).
// ---------------------------------------------------------------------------
__global__ void __launch_bounds__(256)
splitT_kernel(const float* __restrict__ X,
              __nv_bfloat16* __restrict__ xh, __nv_bfloat16* __restrict__ xl,
              __nv_bfloat16* __restrict__ xth, __nv_bfloat16* __restrict__ xtl)
{
    __shared__ float tile[32][33];
    const long base = (long)blockIdx.z * 262144;
    const int tx = threadIdx.x, ty = threadIdx.y;
    const int x = blockIdx.x * 32 + tx;
    const int y0 = blockIdx.y * 32;

#pragma unroll
    for (int j = 0; j < 32; j += 8) {
        long idx = base + (long)(y0 + ty + j) * 512 + x;
        float v = X[idx];
        tile[ty + j][tx] = v;
        __nv_bfloat16 h, l;
        split1(v, h, l);
        xh[idx] = h; xl[idx] = l;
    }
    __syncthreads();

    const int xo = blockIdx.y * 32 + tx;
    const int yo0 = blockIdx.x * 32;
#pragma unroll
    for (int j = 0; j < 32; j += 8) {
        long idx = base + (long)(yo0 + ty + j) * 512 + xo;
        float v = tile[tx][ty + j];
        __nv_bfloat16 h, l;
        split1(v, h, l);
        xth[idx] = h; xtl[idx] = l;
    }
}

// ---------------------------------------------------------------------------
// Row softmax over 512: fp32 in, hi/lo bf16 out. 128 thr/row.
// ---------------------------------------------------------------------------
__global__ void __launch_bounds__(128)
softmax512_f32(const float* __restrict__ S,
               __nv_bfloat16* __restrict__ PH, __nv_bfloat16* __restrict__ PL)
{
    __shared__ float redm[4], reds[4];
    const long row = blockIdx.x;
    const int t = threadIdx.x;

    float4 vv = ((const float4*)(S + row * 512))[t];
    float v[4] = {vv.x, vv.y, vv.z, vv.w};

    float m = fmaxf(fmaxf(v[0], v[1]), fmaxf(v[2], v[3]));
#pragma unroll
    for (int o = 16; o; o >>= 1) m = fmaxf(m, __shfl_xor_sync(0xffffffffu, m, o));
    if ((t & 31) == 0) redm[t >> 5] = m;
    __syncthreads();
    m = fmaxf(fmaxf(redm[0], redm[1]), fmaxf(redm[2], redm[3]));

    float s = 0.f;
#pragma unroll
    for (int j = 0; j < 4; ++j) { v[j] = __expf(v[j] - m); s += v[j]; }
#pragma unroll
    for (int o = 16; o; o >>= 1) s += __shfl_xor_sync(0xffffffffu, s, o);
    if ((t & 31) == 0) reds[t >> 5] = s;
    __syncthreads();
    s = reds[0] + reds[1] + reds[2] + reds[3];
    float r = 1.0f / s;

    float4 w = make_float4(v[0] * r, v[1] * r, v[2] * r, v[3] * r);
    uint2 uh, ul;
    split4(w, uh, ul);
    ((uint2*)(PH + row * 512))[t] = uh;
    ((uint2*)(PL + row * 512))[t] = ul;
}

// ---------------------------------------------------------------------------
// Fused column means: z<256 -> pbar from (sh,sl); z>=256 -> qbar from (qh,ql).
// out[b,j] = (1/512) * sum_i (hi+lo)[b,i,j]
// ---------------------------------------------------------------------------
__global__ void __launch_bounds__(512)
meanPQ_kernel(const __nv_bfloat16* __restrict__ ph, const __nv_bfloat16* __restrict__ pl,
              const __nv_bfloat16* __restrict__ qh, const __nv_bfloat16* __restrict__ ql,
              float* __restrict__ pbar, float* __restrict__ qbar)
{
    const int z = blockIdx.x;
    const bool isq = z >= 256;
    const __nv_bfloat16* hi = isq ? qh : ph;
    const __nv_bfloat16* lo = isq ? ql : pl;
    float* out = isq ? qbar : pbar;
    const int b = z & 255;
    const long base = (long)b * 262144 + threadIdx.x;
    float s = 0.f;
#pragma unroll 4
    for (int i = 0; i < 512; ++i) {
        long off = base + (long)i * 512;
        s += __bfloat162float(hi[off]) + __bfloat162float(lo[off]);
    }
    out[b * 512 + threadIdx.x] = s * (1.0f / 512.0f);
}

// ---------------------------------------------------------------------------
// Fused mixbar + final projection. One block per batch b (512 thr):
//   mb[d] = sum_m pbar[b,m] * (hh+hl)[b,m,d]        (into smem)
//   out[b,d] = sum_c mb[c]*W[d,c] + sum_c qbar[b,c]*W[d,512+c]
// ---------------------------------------------------------------------------
__global__ void __launch_bounds__(512)
mixfinal_kernel(const float* __restrict__ pbar, const float* __restrict__ qbar,
                const __nv_bfloat16* __restrict__ hh, const __nv_bfloat16* __restrict__ hl,
                const float* __restrict__ W, float* __restrict__ out)
{
    __shared__ float pb[512], mb[512], qb[512];
    const int b = blockIdx.x, d = threadIdx.x;
    pb[d] = pbar[b * 512 + d];
    qb[d] = qbar[b * 512 + d];
    __syncthreads();

    const long base = (long)b * 262144 + d;
    float s = 0.f;
#pragma unroll 4
    for (int m = 0; m < 512; ++m) {
        long off = base + (long)m * 512;
        s += pb[m] * (__bfloat162float(hh[off]) + __bfloat162float(hl[off]));
    }
    mb[d] = s;
    __syncthreads();

    const float4* w4 = (const float4*)(W + (long)d * 1024);
    float o = 0.f;
#pragma unroll 4
    for (int c4 = 0; c4 < 128; ++c4) {
        float4 w = w4[c4];
        int c = c4 * 4;
        o += mb[c] * w.x + mb[c + 1] * w.y + mb[c + 2] * w.z + mb[c + 3] * w.w;
    }
#pragma unroll 4
    for (int c4 = 128; c4 < 256; ++c4) {
        float4 w = w4[c4];
        int c = c4 * 4 - 512;
        o += qb[c] * w.x + qb[c + 1] * w.y + qb[c + 2] * w.z + qb[c + 3] * w.w;
    }
    out[b * 512 + d] = o;
}

// ---------------------------------------------------------------------------

extern "C" void kernel_launch(void* const* d_in, const int* in_sizes, int n_in,
                              void* d_out, int out_size)
{
    const float* x     = (const float*)d_in[0];
    const float* Win1  = (const float*)d_in[1];
    const float* Wout1 = (const float*)d_in[2];
    const float* Win2  = (const float*)d_in[3];
    const float* Wout2 = (const float*)d_in[4];
    float* out = (float*)d_out;

    __nv_bfloat16 *xh, *xl, *xth, *xtl, *qh, *ql, *sh, *sl, *mh, *ml;
    __nv_bfloat16 *w1h, *w1l, *wo1h, *wo1l, *w2h, *w2l;
    float *sf, *pbar, *qbar;
    cudaGetSymbolAddress((void**)&xh,  g_xh);   cudaGetSymbolAddress((void**)&xl,  g_xl);
    cudaGetSymbolAddress((void**)&xth, g_xth);  cudaGetSymbolAddress((void**)&xtl, g_xtl);
    cudaGetSymbolAddress((void**)&qh,  g_qh);   cudaGetSymbolAddress((void**)&ql,  g_ql);
    cudaGetSymbolAddress((void**)&sh,  g_sh);   cudaGetSymbolAddress((void**)&sl,  g_sl);
    cudaGetSymbolAddress((void**)&mh,  g_mh);   cudaGetSymbolAddress((void**)&ml,  g_ml);
    cudaGetSymbolAddress((void**)&sf,  g_sf);
    cudaGetSymbolAddress((void**)&w1h, g_w1h);  cudaGetSymbolAddress((void**)&w1l, g_w1l);
    cudaGetSymbolAddress((void**)&wo1h,g_wo1h); cudaGetSymbolAddress((void**)&wo1l,g_wo1l);
    cudaGetSymbolAddress((void**)&w2h, g_w2h);  cudaGetSymbolAddress((void**)&w2l, g_w2l);
    cudaGetSymbolAddress((void**)&pbar, g_pbar);
    cudaGetSymbolAddress((void**)&qbar, g_qbar);

    cudaFuncSetAttribute(gemm_hmma<false, false, false>,
                         cudaFuncAttributeMaxDynamicSharedMemorySize, GEMM_DYN_SMEM);
    cudaFuncSetAttribute(gemm_hmma<false, false, true>,
                         cudaFuncAttributeMaxDynamicSharedMemorySize, GEMM_DYN_SMEM);
    cudaFuncSetAttribute(gemm_hmma<true, true, false>,
                         cudaFuncAttributeMaxDynamicSharedMemorySize, GEMM_DYN_SMEM);

    const int  M_FLAT = BATCH * SEQ;     // 131072
    const long LDb = 262144;

    // ---- splits (X split fused with transpose) ----
    wsplit_kernel<<<262144 / 256, 256>>>(
        (const float4*)Win1, (const float4*)Wout1, (const float4*)Win2,
        (uint2*)w1h, (uint2*)w1l, (uint2*)wo1h, (uint2*)wo1l, (uint2*)w2h, (uint2*)w2l);
    splitT_kernel<<<dim3(16, 16, 256), dim3(32, 8)>>>(x, xh, xl, xth, xtl);

    // ---- block 1 ----
    // q1 = X @ Win1^T
    gemm_hmma<false, false, false><<<dim3(4, 1024, 1), 256, GEMM_DYN_SMEM>>>(
        xh, xl, 512, 0, w1h, w1l, 512, 0,
        nullptr, nullptr, nullptr, nullptr, qh, ql, nullptr, 512, 0, 512);
    // S1[b] = q1[b] @ X[b]^T  (fp32 out)
    gemm_hmma<false, false, true><<<dim3(4, 4, 256), 256, GEMM_DYN_SMEM>>>(
        qh, ql, 512, LDb, xh, xl, 512, LDb,
        nullptr, nullptr, nullptr, nullptr, nullptr, nullptr, sf, 512, LDb, 512);
    softmax512_f32<<<M_FLAT, 128>>>(sf, sh, sl);
    // mix1[b] = P1[b] @ X[b]   (B = X^T, K-major over m)
    gemm_hmma<false, false, false><<<dim3(4, 4, 256), 256, GEMM_DYN_SMEM>>>(
        sh, sl, 512, LDb, xth, xtl, 512, LDb,
        nullptr, nullptr, nullptr, nullptr, mh, ml, nullptr, 512, LDb, 512);
    // h = tanh(mix1 @ Wout1[:, :512]^T + q1 @ Wout1[:, 512:]^T) -> overwrite X slots
    gemm_hmma<true, true, false><<<dim3(4, 1024, 1), 256, GEMM_DYN_SMEM>>>(
        mh, ml, 512, 0, wo1h, wo1l, 1024, 0,
        qh, ql, wo1h + 512, wo1l + 512, xh, xl, nullptr, 512, 0, 512);

    // ---- block 2 (pooling collapsed: no mix2 / out-proj GEMMs) ----
    // q2 = h @ Win2^T
    gemm_hmma<false, false, false><<<dim3(4, 1024, 1), 256, GEMM_DYN_SMEM>>>(
        xh, xl, 512, 0, w2h, w2l, 512, 0,
        nullptr, nullptr, nullptr, nullptr, qh, ql, nullptr, 512, 0, 512);
    // S2[b] = q2[b] @ h[b]^T  (fp32 out)
    gemm_hmma<false, false, true><<<dim3(4, 4, 256), 256, GEMM_DYN_SMEM>>>(
        qh, ql, 512, LDb, xh, xl, 512, LDb,
        nullptr, nullptr, nullptr, nullptr, nullptr, nullptr, sf, 512, LDb, 512);
    softmax512_f32<<<M_FLAT, 128>>>(sf, sh, sl);

    // ---- fused tail ----
    meanPQ_kernel<<<512, 512>>>(sh, sl, qh, ql, pbar, qbar);
    mixfinal_kernel<<<BATCH, 512>>>(pbar, qbar, xh, xl, Wout2, out);
}

// round 13
// speedup vs baseline: 1.0348x; 1.0341x over previous
#include <cuda_runtime.h>
#include <cuda_bf16.h>
#include <math.h>
#include <stdint.h>

#define BATCH 256
#define SEQ   512
#define DIM   512

static const long NEL = (long)BATCH * SEQ * DIM;  // 67108864

// ---------------------------------------------------------------------------
// Scratch: __device__ globals (allocation-free rule)
// ---------------------------------------------------------------------------
static __device__ __nv_bfloat16 g_xh[67108864], g_xl[67108864];   // X / later h
static __device__ __nv_bfloat16 g_xth[67108864], g_xtl[67108864]; // X^T (block 1)
static __device__ __nv_bfloat16 g_qh[67108864], g_ql[67108864];   // q1 / q2
static __device__ __nv_bfloat16 g_sh[67108864], g_sl[67108864];   // P1 hi/lo
static __device__ __nv_bfloat16 g_mh[67108864], g_ml[67108864];   // mix1
static __device__ float g_sf[67108864];                           // scores fp32
static __device__ __nv_bfloat16 g_w1h[262144], g_w1l[262144];
static __device__ __nv_bfloat16 g_wo1h[524288], g_wo1l[524288];
static __device__ __nv_bfloat16 g_w2h[262144], g_w2l[262144];
static __device__ float g_pbar4[524288];   // [4][256][512] partial col sums
static __device__ float g_qbar[131072];

// ---------------------------------------------------------------------------
// PTX helpers (sm_80+ baseline: cp.async / ldmatrix / mma.sync bf16)
// ---------------------------------------------------------------------------
__device__ __forceinline__ void cp_async16(uint32_t s, const void* g) {
    asm volatile("cp.async.cg.shared.global [%0], [%1], 16;"
                 :: "r"(s), "l"(__cvta_generic_to_global(g)) : "memory");
}

__device__ __forceinline__ void ldsm_x4(uint32_t addr, uint32_t& r0, uint32_t& r1,
                                        uint32_t& r2, uint32_t& r3) {
    asm volatile("ldmatrix.sync.aligned.m8n8.x4.shared.b16 {%0,%1,%2,%3}, [%4];"
                 : "=r"(r0), "=r"(r1), "=r"(r2), "=r"(r3) : "r"(addr));
}

__device__ __forceinline__ void mma16816(float* c, const uint32_t* a, const uint32_t* b) {
    asm volatile("mma.sync.aligned.m16n8k16.row.col.f32.bf16.bf16.f32 "
                 "{%0,%1,%2,%3}, {%4,%5,%6,%7}, {%8,%9}, {%0,%1,%2,%3};"
                 : "+f"(c[0]), "+f"(c[1]), "+f"(c[2]), "+f"(c[3])
                 : "r"(a[0]), "r"(a[1]), "r"(a[2]), "r"(a[3]), "r"(b[0]), "r"(b[1]));
}

// ---------------------------------------------------------------------------
// Split-bf16 HMMA GEMM (R10-proven mainloop).
//   C[m,n] = sum_k A[m,k]*B[n,k], A=aH+aL, B=bH+bL; AH*BH + AH*BL + AL*BH.
//   Block tile 128x128, BK=32, 256 thr (2x4 warps, 64x32 warp tile).
//   SMEM rows 128B = [hi 64B | lo 64B], XOR swizzle. 3-stage cp.async
//   pipeline (wait_group 1), one __syncthreads per chunk.
// ---------------------------------------------------------------------------
#define BK      32
#define TILE_B  (128 * 128)           // 16384 B: one operand (hi+lo packed)
#define STAGE_B (2 * TILE_B)          // A, B
#define NSTAGE  3
#define GEMM_DYN_SMEM (NSTAGE * STAGE_B)   // 98304 B

// granule g (16B) at row r -> g ^ (r&7) within the 128B row
__device__ __forceinline__ void load_chunk(uint32_t sbase,
    const __nv_bfloat16* pAH, const __nv_bfloat16* pAL,
    const __nv_bfloat16* pBH, const __nv_bfloat16* pBL,
    long rowA, long colB, int lda, int ldb, int k0, int tid)
{
#pragma unroll
    for (int i = 0; i < 8; ++i) {
        int seg = tid + i * 256;            // 0..2047 16B segments
        int t   = seg >> 10;                // 0=A, 1=B
        int r   = (seg >> 3) & 127;         // row 0..127
        int g   = seg & 7;                  // granule 0..7 (0-3 hi, 4-7 lo)
        int c16 = g & 3;
        const __nv_bfloat16* src =
            (t ? ((g & 4) ? pBL : pBH) : ((g & 4) ? pAL : pAH));
        long row0 = t ? colB : rowA;
        int  ld   = t ? ldb  : lda;
        cp_async16(sbase + (uint32_t)(t * TILE_B + r * 128 + ((g ^ (r & 7)) * 16)),
                   src + (row0 + r) * (long)ld + k0 + c16 * 8);
    }
    asm volatile("cp.async.commit_group;" ::: "memory");
}

template<bool DUAL, bool TANH, bool OUTF32>
__global__ void __launch_bounds__(256, 2)
gemm_hmma(const __nv_bfloat16* __restrict__ aH, const __nv_bfloat16* __restrict__ aL,
          int lda, long sA,
          const __nv_bfloat16* __restrict__ bH, const __nv_bfloat16* __restrict__ bL,
          int ldb, long sB,
          const __nv_bfloat16* __restrict__ a2H, const __nv_bfloat16* __restrict__ a2L,
          const __nv_bfloat16* __restrict__ b2H, const __nv_bfloat16* __restrict__ b2L,
          __nv_bfloat16* __restrict__ cH, __nv_bfloat16* __restrict__ cL,
          float* __restrict__ cF,
          int ldc, long sC, int K)
{
    extern __shared__ char smem_raw[];
    const uint32_t smem = (uint32_t)__cvta_generic_to_shared(smem_raw);

    const int tid  = threadIdx.x;
    const int lane = tid & 31;
    const int wid  = tid >> 5;
    const int wm   = wid & 1;       // 2 m-groups of 64
    const int wn   = wid >> 1;      // 4 n-groups of 32
    const int bz   = blockIdx.z;
    const long rowA = (long)blockIdx.y * 128;
    const long colB = (long)blockIdx.x * 128;

    float acc[4][4][4];
#pragma unroll
    for (int i = 0; i < 4; ++i)
#pragma unroll
        for (int j = 0; j < 4; ++j)
#pragma unroll
            for (int k = 0; k < 4; ++k) acc[i][j][k] = 0.f;

    const int npc    = K / BK;                 // chunks per pair
    const int nchunk = (DUAL ? 2 : 1) * npc;

    const __nv_bfloat16* AH0 = aH + bz * sA;
    const __nv_bfloat16* AL0 = aL + bz * sA;
    const __nv_bfloat16* BH0 = bH + bz * sB;
    const __nv_bfloat16* BL0 = bL + bz * sB;
    const __nv_bfloat16* AH1 = DUAL ? a2H + bz * sA : nullptr;
    const __nv_bfloat16* AL1 = DUAL ? a2L + bz * sA : nullptr;
    const __nv_bfloat16* BH1 = DUAL ? b2H + bz * sB : nullptr;
    const __nv_bfloat16* BL1 = DUAL ? b2L + bz * sB : nullptr;

    // Per-thread fragment address constants (swizzle folded in; row&7 == lane&7).
    const uint32_t aRowB = (uint32_t)((wm * 64 + (lane & 15)) * 128);
    const uint32_t bRowB = (uint32_t)((wn * 32 + ((lane >> 4) << 3) + (lane & 7)) * 128);
    uint32_t gA16[2], gB16[2];
#pragma unroll
    for (int ks = 0; ks < 2; ++ks) {
        gA16[ks] = (uint32_t)(((ks * 2 + (lane >> 4)) ^ (lane & 7)) * 16);
        gB16[ks] = (uint32_t)(((ks * 2 + ((lane >> 3) & 1)) ^ (lane & 7)) * 16);
    }

    // prologue: chunks 0,1 -> stages 0,1 (all GEMMs here have nchunk >= 16)
    load_chunk(smem,           AH0, AL0, BH0, BL0, rowA, colB, lda, ldb, 0,  tid);
    load_chunk(smem + STAGE_B, AH0, AL0, BH0, BL0, rowA, colB, lda, ldb, BK, tid);

    for (int c = 0; c < nchunk; ++c) {
        if (c + 1 < nchunk)
            asm volatile("cp.async.wait_group 1;" ::: "memory");
        else
            asm volatile("cp.async.wait_group 0;" ::: "memory");
        __syncthreads();   // stage c%3 ready; all warps done with stage (c-1)%3

        if (c + 2 < nchunk) {
            int cn = c + 2;
            int p  = cn / npc;
            int k0 = (cn % npc) * BK;
            uint32_t dst = smem + (uint32_t)((cn % NSTAGE) * STAGE_B);
            if (!DUAL || p == 0)
                load_chunk(dst, AH0, AL0, BH0, BL0, rowA, colB, lda, ldb, k0, tid);
            else
                load_chunk(dst, AH1, AL1, BH1, BL1, rowA, colB, lda, ldb, k0, tid);
        }

        const uint32_t sA_ = smem + (uint32_t)((c % NSTAGE) * STAGE_B);
        const uint32_t sB_ = sA_ + TILE_B;

#pragma unroll
        for (int ks = 0; ks < 2; ++ks) {
            uint32_t bhf[4][2], blf[4][2];
#pragma unroll
            for (int np = 0; np < 2; ++np) {
                uint32_t boff = bRowB + (uint32_t)(np * 16 * 128);
                ldsm_x4(sB_ + boff + gB16[ks], bhf[2 * np][0], bhf[2 * np][1],
                                               bhf[2 * np + 1][0], bhf[2 * np + 1][1]);
                ldsm_x4(sB_ + (boff + gB16[ks] ^ 64u), blf[2 * np][0], blf[2 * np][1],
                                               blf[2 * np + 1][0], blf[2 * np + 1][1]);
            }
#pragma unroll
            for (int mf = 0; mf < 4; ++mf) {
                uint32_t aoff = aRowB + (uint32_t)(mf * 16 * 128);
                uint32_t ahf[4], alf[4];
                ldsm_x4(sA_ + aoff + gA16[ks], ahf[0], ahf[1], ahf[2], ahf[3]);
                ldsm_x4(sA_ + (aoff + gA16[ks] ^ 64u), alf[0], alf[1], alf[2], alf[3]);
#pragma unroll
                for (int nf = 0; nf < 4; ++nf) {
                    mma16816(acc[mf][nf], ahf, bhf[nf]);  // hi*hi
                    mma16816(acc[mf][nf], ahf, blf[nf]);  // hi*lo
                    mma16816(acc[mf][nf], alf, bhf[nf]);  // lo*hi
                }
            }
        }
    }

    // Epilogue: c0,c1 -> (row=rq, col=cq..cq+1); c2,c3 -> row+8.
    const int rq = lane >> 2, cq = (lane & 3) * 2;

#pragma unroll
    for (int mf = 0; mf < 4; ++mf) {
#pragma unroll
        for (int nf = 0; nf < 4; ++nf) {
            long col = colB + wn * 32 + nf * 8 + cq;
#pragma unroll
            for (int half = 0; half < 2; ++half) {
                long row = rowA + wm * 64 + mf * 16 + rq + half * 8;
                float v0 = acc[mf][nf][half * 2 + 0];
                float v1 = acc[mf][nf][half * 2 + 1];
                if (OUTF32) {
                    float* CF = cF + (long)bz * sC;
                    *(float2*)(CF + row * (long)ldc + col) = make_float2(v0, v1);
                } else {
                    if (TANH) { v0 = tanhf(v0); v1 = tanhf(v1); }
                    __nv_bfloat16 h0 = __float2bfloat16_rn(v0);
                    __nv_bfloat16 h1 = __float2bfloat16_rn(v1);
                    __nv_bfloat16 l0 = __float2bfloat16_rn(v0 - __bfloat162float(h0));
                    __nv_bfloat16 l1 = __float2bfloat16_rn(v1 - __bfloat162float(h1));
                    __nv_bfloat162 hp; hp.x = h0; hp.y = h1;
                    __nv_bfloat162 lp; lp.x = l0; lp.y = l1;
                    __nv_bfloat16* CH = cH + (long)bz * sC;
                    __nv_bfloat16* CL = cL + (long)bz * sC;
                    *(__nv_bfloat162*)(CH + row * (long)ldc + col) = hp;
                    *(__nv_bfloat162*)(CL + row * (long)ldc + col) = lp;
                }
            }
        }
    }
}

// ---------------------------------------------------------------------------
// fp32 -> (hi, lo) bf16 split helpers
// ---------------------------------------------------------------------------
__device__ __forceinline__ void split4(float4 v, uint2& uh, uint2& ul)
{
    float f[4] = {v.x, v.y, v.z, v.w};
    __nv_bfloat16 h[4], l[4];
#pragma unroll
    for (int j = 0; j < 4; ++j) {
        h[j] = __float2bfloat16_rn(f[j]);
        l[j] = __float2bfloat16_rn(f[j] - __bfloat162float(h[j]));
    }
    __nv_bfloat162 h01, h23, l01, l23;
    h01.x = h[0]; h01.y = h[1]; h23.x = h[2]; h23.y = h[3];
    l01.x = l[0]; l01.y = l[1]; l23.x = l[2]; l23.y = l[3];
    uh.x = *(uint32_t*)&h01; uh.y = *(uint32_t*)&h23;
    ul.x = *(uint32_t*)&l01; ul.y = *(uint32_t*)&l23;
}

__device__ __forceinline__ void split1(float f, __nv_bfloat16& h, __nv_bfloat16& l)
{
    h = __float2bfloat16_rn(f);
    l = __float2bfloat16_rn(f - __bfloat162float(h));
}

// Fused weight split: W1 (65536 f4) | Wout1 (131072 f4) | W2 (65536 f4)
__global__ void __launch_bounds__(256)
wsplit_kernel(const float4* __restrict__ w1, const float4* __restrict__ wo1,
              const float4* __restrict__ w2,
              uint2* __restrict__ w1h, uint2* __restrict__ w1l,
              uint2* __restrict__ wo1h, uint2* __restrict__ wo1l,
              uint2* __restrict__ w2h, uint2* __restrict__ w2l)
{
    long i = (long)blockIdx.x * blockDim.x + threadIdx.x;
    const float4* src; uint2 *dh, *dl; long j;
    if (i < 65536)       { src = w1;  dh = w1h;  dl = w1l;  j = i; }
    else if (i < 196608) { src = wo1; dh = wo1h; dl = wo1l; j = i - 65536; }
    else                 { src = w2;  dh = w2h;  dl = w2l;  j = i - 196608; }
    uint2 uh, ul;
    split4(src[j], uh, ul);
    dh[j] = uh; dl[j] = ul;
}

// ---------------------------------------------------------------------------
// Fused X split + transpose: reads X fp32 once, writes xh/xl (row-major) and
// xth/xtl (transposed). 32x32 tiles, block (32,8), grid (16,16,256).
// ---------------------------------------------------------------------------
__global__ void __launch_bounds__(256)
splitT_kernel(const float* __restrict__ X,
              __nv_bfloat16* __restrict__ xh, __nv_bfloat16* __restrict__ xl,
              __nv_bfloat16* __restrict__ xth, __nv_bfloat16* __restrict__ xtl)
{
    __shared__ float tile[32][33];
    const long base = (long)blockIdx.z * 262144;
    const int tx = threadIdx.x, ty = threadIdx.y;
    const int x = blockIdx.x * 32 + tx;
    const int y0 = blockIdx.y * 32;

#pragma unroll
    for (int j = 0; j < 32; j += 8) {
        long idx = base + (long)(y0 + ty + j) * 512 + x;
        float v = X[idx];
        tile[ty + j][tx] = v;
        __nv_bfloat16 h, l;
        split1(v, h, l);
        xh[idx] = h; xl[idx] = l;
    }
    __syncthreads();

    const int xo = blockIdx.y * 32 + tx;
    const int yo0 = blockIdx.x * 32;
#pragma unroll
    for (int j = 0; j < 32; j += 8) {
        long idx = base + (long)(yo0 + ty + j) * 512 + xo;
        float v = tile[tx][ty + j];
        __nv_bfloat16 h, l;
        split1(v, h, l);
        xth[idx] = h; xtl[idx] = l;
    }
}

// ---------------------------------------------------------------------------
// Row softmax over 512: fp32 in, hi/lo bf16 out (block 1 -- P feeds a GEMM).
// ---------------------------------------------------------------------------
__global__ void __launch_bounds__(128)
softmax512_f32(const float* __restrict__ S,
               __nv_bfloat16* __restrict__ PH, __nv_bfloat16* __restrict__ PL)
{
    __shared__ float redm[4], reds[4];
    const long row = blockIdx.x;
    const int t = threadIdx.x;

    float4 vv = ((const float4*)(S + row * 512))[t];
    float v[4] = {vv.x, vv.y, vv.z, vv.w};

    float m = fmaxf(fmaxf(v[0], v[1]), fmaxf(v[2], v[3]));
#pragma unroll
    for (int o = 16; o; o >>= 1) m = fmaxf(m, __shfl_xor_sync(0xffffffffu, m, o));
    if ((t & 31) == 0) redm[t >> 5] = m;
    __syncthreads();
    m = fmaxf(fmaxf(redm[0], redm[1]), fmaxf(redm[2], redm[3]));

    float s = 0.f;
#pragma unroll
    for (int j = 0; j < 4; ++j) { v[j] = __expf(v[j] - m); s += v[j]; }
#pragma unroll
    for (int o = 16; o; o >>= 1) s += __shfl_xor_sync(0xffffffffu, s, o);
    if ((t & 31) == 0) reds[t >> 5] = s;
    __syncthreads();
    s = reds[0] + reds[1] + reds[2] + reds[3];
    float r = 1.0f / s;

    float4 w = make_float4(v[0] * r, v[1] * r, v[2] * r, v[3] * r);
    uint2 uh, ul;
    split4(w, uh, ul);
    ((uint2*)(PH + row * 512))[t] = uh;
    ((uint2*)(PL + row * 512))[t] = ul;
}

// ---------------------------------------------------------------------------
// Block-2 fused softmax + column-sum (P2 never materialized).
// Grid (4, 256): block (rg, b) handles rows [rg*128, rg*128+128) of batch b.
// 256 thr = 8 warps; warp w processes 16 rows serially. Each row: warp-wide
// softmax in registers (lane owns cols lane+32j, j<16), accumulate weights
// into per-lane column partials. Block-reduce across warps in smem, write
// per-block partials to pbar4[rg][b][col]. mixfinal sums the 4 partials.
// ---------------------------------------------------------------------------
__global__ void __launch_bounds__(256)
softmax_colmean_kernel(const float* __restrict__ S, float* __restrict__ pbar4)
{
    __shared__ float part[8][512];
    const int b = blockIdx.y, rg = blockIdx.x;
    const int wid = threadIdx.x >> 5, lane = threadIdx.x & 31;

    const float* Sb = S + (long)b * 262144 + (long)(rg * 128 + wid * 16) * 512;

    float csum[16];
#pragma unroll
    for (int j = 0; j < 16; ++j) csum[j] = 0.f;

    for (int r = 0; r < 16; ++r) {
        const float* row = Sb + (long)r * 512;
        float v[16];
#pragma unroll
        for (int j = 0; j < 16; ++j) v[j] = row[lane + 32 * j];
        float m = v[0];
#pragma unroll
        for (int j = 1; j < 16; ++j) m = fmaxf(m, v[j]);
#pragma unroll
        for (int o = 16; o; o >>= 1) m = fmaxf(m, __shfl_xor_sync(0xffffffffu, m, o));
        float s = 0.f;
#pragma unroll
        for (int j = 0; j < 16; ++j) { v[j] = __expf(v[j] - m); s += v[j]; }
#pragma unroll
        for (int o = 16; o; o >>= 1) s += __shfl_xor_sync(0xffffffffu, s, o);
        float inv = 1.0f / s;
#pragma unroll
        for (int j = 0; j < 16; ++j) csum[j] += v[j] * inv;
    }

#pragma unroll
    for (int j = 0; j < 16; ++j) part[wid][lane + 32 * j] = csum[j];
    __syncthreads();

    // 256 threads x 2 cols: sum 8 warp partials, write block partial.
#pragma unroll
    for (int cc = 0; cc < 2; ++cc) {
        int col = threadIdx.x + cc * 256;
        float s = 0.f;
#pragma unroll
        for (int w = 0; w < 8; ++w) s += part[w][col];
        pbar4[((long)rg * 256 + b) * 512 + col] = s;
    }
}

// ---------------------------------------------------------------------------
// qbar[b,j] = (1/512) * sum_i (hi+lo)(q2)[b,i,j]
// ---------------------------------------------------------------------------
__global__ void __launch_bounds__(512)
meanQ_kernel(const __nv_bfloat16* __restrict__ hi, const __nv_bfloat16* __restrict__ lo,
             float* __restrict__ qbar)
{
    const long base = (long)blockIdx.x * 262144 + threadIdx.x;
    float s = 0.f;
#pragma unroll 4
    for (int i = 0; i < 512; ++i) {
        long off = base + (long)i * 512;
        s += __bfloat162float(hi[off]) + __bfloat162float(lo[off]);
    }
    qbar[blockIdx.x * 512 + threadIdx.x] = s * (1.0f / 512.0f);
}

// ---------------------------------------------------------------------------
// Fused mixbar + final projection. One block per batch b (512 thr):
//   pb[d] = (1/512) * sum_rg pbar4[rg][b][d]
//   mb[d] = sum_m pb[m] * (hh+hl)[b,m,d]
//   out[b,d] = sum_c mb[c]*W[d,c] + sum_c qbar[b,c]*W[d,512+c]
// ---------------------------------------------------------------------------
__global__ void __launch_bounds__(512)
mixfinal_kernel(const float* __restrict__ pbar4, const float* __restrict__ qbar,
                const __nv_bfloat16* __restrict__ hh, const __nv_bfloat16* __restrict__ hl,
                const float* __restrict__ W, float* __restrict__ out)
{
    __shared__ float pb[512], mb[512], qb[512];
    const int b = blockIdx.x, d = threadIdx.x;
    float p = 0.f;
#pragma unroll
    for (int rg = 0; rg < 4; ++rg)
        p += pbar4[((long)rg * 256 + b) * 512 + d];
    pb[d] = p * (1.0f / 512.0f);
    qb[d] = qbar[b * 512 + d];
    __syncthreads();

    const long base = (long)b * 262144 + d;
    float s = 0.f;
#pragma unroll 4
    for (int m = 0; m < 512; ++m) {
        long off = base + (long)m * 512;
        s += pb[m] * (__bfloat162float(hh[off]) + __bfloat162float(hl[off]));
    }
    mb[d] = s;
    __syncthreads();

    const float4* w4 = (const float4*)(W + (long)d * 1024);
    float o = 0.f;
#pragma unroll 4
    for (int c4 = 0; c4 < 128; ++c4) {
        float4 w = w4[c4];
        int c = c4 * 4;
        o += mb[c] * w.x + mb[c + 1] * w.y + mb[c + 2] * w.z + mb[c + 3] * w.w;
    }
#pragma unroll 4
    for (int c4 = 128; c4 < 256; ++c4) {
        float4 w = w4[c4];
        int c = c4 * 4 - 512;
        o += qb[c] * w.x + qb[c + 1] * w.y + qb[c + 2] * w.z + qb[c + 3] * w.w;
    }
    out[b * 512 + d] = o;
}

// ---------------------------------------------------------------------------

extern "C" void kernel_launch(void* const* d_in, const int* in_sizes, int n_in,
                              void* d_out, int out_size)
{
    const float* x     = (const float*)d_in[0];
    const float* Win1  = (const float*)d_in[1];
    const float* Wout1 = (const float*)d_in[2];
    const float* Win2  = (const float*)d_in[3];
    const float* Wout2 = (const float*)d_in[4];
    float* out = (float*)d_out;

    __nv_bfloat16 *xh, *xl, *xth, *xtl, *qh, *ql, *sh, *sl, *mh, *ml;
    __nv_bfloat16 *w1h, *w1l, *wo1h, *wo1l, *w2h, *w2l;
    float *sf, *pbar4, *qbar;
    cudaGetSymbolAddress((void**)&xh,  g_xh);   cudaGetSymbolAddress((void**)&xl,  g_xl);
    cudaGetSymbolAddress((void**)&xth, g_xth);  cudaGetSymbolAddress((void**)&xtl, g_xtl);
    cudaGetSymbolAddress((void**)&qh,  g_qh);   cudaGetSymbolAddress((void**)&ql,  g_ql);
    cudaGetSymbolAddress((void**)&sh,  g_sh);   cudaGetSymbolAddress((void**)&sl,  g_sl);
    cudaGetSymbolAddress((void**)&mh,  g_mh);   cudaGetSymbolAddress((void**)&ml,  g_ml);
    cudaGetSymbolAddress((void**)&sf,  g_sf);
    cudaGetSymbolAddress((void**)&w1h, g_w1h);  cudaGetSymbolAddress((void**)&w1l, g_w1l);
    cudaGetSymbolAddress((void**)&wo1h,g_wo1h); cudaGetSymbolAddress((void**)&wo1l,g_wo1l);
    cudaGetSymbolAddress((void**)&w2h, g_w2h);  cudaGetSymbolAddress((void**)&w2l, g_w2l);
    cudaGetSymbolAddress((void**)&pbar4, g_pbar4);
    cudaGetSymbolAddress((void**)&qbar,  g_qbar);

    cudaFuncSetAttribute(gemm_hmma<false, false, false>,
                         cudaFuncAttributeMaxDynamicSharedMemorySize, GEMM_DYN_SMEM);
    cudaFuncSetAttribute(gemm_hmma<false, false, true>,
                         cudaFuncAttributeMaxDynamicSharedMemorySize, GEMM_DYN_SMEM);
    cudaFuncSetAttribute(gemm_hmma<true, true, false>,
                         cudaFuncAttributeMaxDynamicSharedMemorySize, GEMM_DYN_SMEM);

    const int  M_FLAT = BATCH * SEQ;     // 131072
    const long LDb = 262144;

    // ---- splits (X split fused with transpose) ----
    wsplit_kernel<<<262144 / 256, 256>>>(
        (const float4*)Win1, (const float4*)Wout1, (const float4*)Win2,
        (uint2*)w1h, (uint2*)w1l, (uint2*)wo1h, (uint2*)wo1l, (uint2*)w2h, (uint2*)w2l);
    splitT_kernel<<<dim3(16, 16, 256), dim3(32, 8)>>>(x, xh, xl, xth, xtl);

    // ---- block 1 ----
    // q1 = X @ Win1^T
    gemm_hmma<false, false, false><<<dim3(4, 1024, 1), 256, GEMM_DYN_SMEM>>>(
        xh, xl, 512, 0, w1h, w1l, 512, 0,
        nullptr, nullptr, nullptr, nullptr, qh, ql, nullptr, 512, 0, 512);
    // S1[b] = q1[b] @ X[b]^T  (fp32 out)
    gemm_hmma<false, false, true><<<dim3(4, 4, 256), 256, GEMM_DYN_SMEM>>>(
        qh, ql, 512, LDb, xh, xl, 512, LDb,
        nullptr, nullptr, nullptr, nullptr, nullptr, nullptr, sf, 512, LDb, 512);
    softmax512_f32<<<M_FLAT, 128>>>(sf, sh, sl);
    // mix1[b] = P1[b] @ X[b]   (B = X^T, K-major over m)
    gemm_hmma<false, false, false><<<dim3(4, 4, 256), 256, GEMM_DYN_SMEM>>>(
        sh, sl, 512, LDb, xth, xtl, 512, LDb,
        nullptr, nullptr, nullptr, nullptr, mh, ml, nullptr, 512, LDb, 512);
    // h = tanh(mix1 @ Wout1[:, :512]^T + q1 @ Wout1[:, 512:]^T) -> overwrite X slots
    gemm_hmma<true, true, false><<<dim3(4, 1024, 1), 256, GEMM_DYN_SMEM>>>(
        mh, ml, 512, 0, wo1h, wo1l, 1024, 0,
        qh, ql, wo1h + 512, wo1l + 512, xh, xl, nullptr, 512, 0, 512);

    // ---- block 2 (pooling collapsed: no mix2 / out-proj GEMMs) ----
    // q2 = h @ Win2^T
    gemm_hmma<false, false, false><<<dim3(4, 1024, 1), 256, GEMM_DYN_SMEM>>>(
        xh, xl, 512, 0, w2h, w2l, 512, 0,
        nullptr, nullptr, nullptr, nullptr, qh, ql, nullptr, 512, 0, 512);
    // S2[b] = q2[b] @ h[b]^T  (fp32 out)
    gemm_hmma<false, false, true><<<dim3(4, 4, 256), 256, GEMM_DYN_SMEM>>>(
        qh, ql, 512, LDb, xh, xl, 512, LDb,
        nullptr, nullptr, nullptr, nullptr, nullptr, nullptr, sf, 512, LDb, 512);

    // ---- fused tail: softmax(S2) column means without materializing P2 ----
    softmax_colmean_kernel<<<dim3(4, 256), 256>>>(sf, pbar4);
    meanQ_kernel<<<BATCH, 512>>>(qh, ql, qbar);
    mixfinal_kernel<<<BATCH, 512>>>(pbar4, qbar, xh, xl, Wout2, out);
}

// round 14
// speedup vs baseline: 1.1016x; 1.0646x over previous
#include <cuda_runtime.h>
#include <cuda_bf16.h>
#include <math.h>
#include <stdint.h>

#define BATCH 256
#define SEQ   512
#define DIM   512

static const long NEL = (long)BATCH * SEQ * DIM;  // 67108864

// ---------------------------------------------------------------------------
// Scratch: __device__ globals (allocation-free rule)
// ---------------------------------------------------------------------------
static __device__ __nv_bfloat16 g_xh[67108864], g_xl[67108864];   // X / later h
static __device__ __nv_bfloat16 g_xth[67108864], g_xtl[67108864]; // X^T (block 1)
static __device__ __nv_bfloat16 g_qh[67108864], g_ql[67108864];   // q1 / q2
static __device__ __nv_bfloat16 g_sh[67108864], g_sl[67108864];   // P1 hi/lo
static __device__ __nv_bfloat16 g_mh[67108864], g_ml[67108864];   // mix1
static __device__ float g_sf[67108864];                           // scores fp32
static __device__ __nv_bfloat16 g_w1h[262144], g_w1l[262144];
static __device__ __nv_bfloat16 g_wo1h[524288], g_wo1l[524288];
static __device__ __nv_bfloat16 g_w2h[262144], g_w2l[262144];
static __device__ float g_pbar4[524288];   // [4][256][512] partial col sums
static __device__ float g_qbar[131072];

// ---------------------------------------------------------------------------
// PTX helpers (sm_80+ baseline: cp.async / ldmatrix / mma.sync bf16)
// ---------------------------------------------------------------------------
__device__ __forceinline__ void cp_async16(uint32_t s, const void* g) {
    asm volatile("cp.async.cg.shared.global [%0], [%1], 16;"
                 :: "r"(s), "l"(__cvta_generic_to_global(g)) : "memory");
}

__device__ __forceinline__ void ldsm_x4(uint32_t addr, uint32_t& r0, uint32_t& r1,
                                        uint32_t& r2, uint32_t& r3) {
    asm volatile("ldmatrix.sync.aligned.m8n8.x4.shared.b16 {%0,%1,%2,%3}, [%4];"
                 : "=r"(r0), "=r"(r1), "=r"(r2), "=r"(r3) : "r"(addr));
}

__device__ __forceinline__ void mma16816(float* c, const uint32_t* a, const uint32_t* b) {
    asm volatile("mma.sync.aligned.m16n8k16.row.col.f32.bf16.bf16.f32 "
                 "{%0,%1,%2,%3}, {%4,%5,%6,%7}, {%8,%9}, {%0,%1,%2,%3};"
                 : "+f"(c[0]), "+f"(c[1]), "+f"(c[2]), "+f"(c[3])
                 : "r"(a[0]), "r"(a[1]), "r"(a[2]), "r"(a[3]), "r"(b[0]), "r"(b[1]));
}

// ---------------------------------------------------------------------------
// Split-bf16 HMMA GEMM (R10-proven mainloop).
//   C[m,n] = sum_k A[m,k]*B[n,k], A=aH+aL, B=bH+bL.
//   THREE=1: AH*BH + AH*BL + AL*BH  (full 3-pass, ~2^-18 error)
//   THREE=0: AH*BH + AH*BL          (2-pass, ~2^-9 error -- block-2 only,
//                                    where mean-pooling suppresses it)
//   Block tile 128x128, BK=32, 256 thr (2x4 warps, 64x32 warp tile).
//   SMEM rows 128B = [hi 64B | lo 64B], XOR swizzle. 3-stage cp.async
//   pipeline (wait_group 1), one __syncthreads per chunk.
// ---------------------------------------------------------------------------
#define BK      32
#define TILE_B  (128 * 128)           // 16384 B: one operand (hi+lo packed)
#define STAGE_B (2 * TILE_B)          // A, B
#define NSTAGE  3
#define GEMM_DYN_SMEM (NSTAGE * STAGE_B)   // 98304 B

// granule g (16B) at row r -> g ^ (r&7) within the 128B row
__device__ __forceinline__ void load_chunk(uint32_t sbase,
    const __nv_bfloat16* pAH, const __nv_bfloat16* pAL,
    const __nv_bfloat16* pBH, const __nv_bfloat16* pBL,
    long rowA, long colB, int lda, int ldb, int k0, int tid)
{
#pragma unroll
    for (int i = 0; i < 8; ++i) {
        int seg = tid + i * 256;            // 0..2047 16B segments
        int t   = seg >> 10;                // 0=A, 1=B
        int r   = (seg >> 3) & 127;         // row 0..127
        int g   = seg & 7;                  // granule 0..7 (0-3 hi, 4-7 lo)
        int c16 = g & 3;
        const __nv_bfloat16* src =
            (t ? ((g & 4) ? pBL : pBH) : ((g & 4) ? pAL : pAH));
        long row0 = t ? colB : rowA;
        int  ld   = t ? ldb  : lda;
        cp_async16(sbase + (uint32_t)(t * TILE_B + r * 128 + ((g ^ (r & 7)) * 16)),
                   src + (row0 + r) * (long)ld + k0 + c16 * 8);
    }
    asm volatile("cp.async.commit_group;" ::: "memory");
}

template<bool DUAL, bool TANH, bool OUTF32, bool THREE>
__global__ void __launch_bounds__(256, 2)
gemm_hmma(const __nv_bfloat16* __restrict__ aH, const __nv_bfloat16* __restrict__ aL,
          int lda, long sA,
          const __nv_bfloat16* __restrict__ bH, const __nv_bfloat16* __restrict__ bL,
          int ldb, long sB,
          const __nv_bfloat16* __restrict__ a2H, const __nv_bfloat16* __restrict__ a2L,
          const __nv_bfloat16* __restrict__ b2H, const __nv_bfloat16* __restrict__ b2L,
          __nv_bfloat16* __restrict__ cH, __nv_bfloat16* __restrict__ cL,
          float* __restrict__ cF,
          int ldc, long sC, int K)
{
    extern __shared__ char smem_raw[];
    const uint32_t smem = (uint32_t)__cvta_generic_to_shared(smem_raw);

    const int tid  = threadIdx.x;
    const int lane = tid & 31;
    const int wid  = tid >> 5;
    const int wm   = wid & 1;       // 2 m-groups of 64
    const int wn   = wid >> 1;      // 4 n-groups of 32
    const int bz   = blockIdx.z;
    const long rowA = (long)blockIdx.y * 128;
    const long colB = (long)blockIdx.x * 128;

    float acc[4][4][4];
#pragma unroll
    for (int i = 0; i < 4; ++i)
#pragma unroll
        for (int j = 0; j < 4; ++j)
#pragma unroll
            for (int k = 0; k < 4; ++k) acc[i][j][k] = 0.f;

    const int npc    = K / BK;                 // chunks per pair
    const int nchunk = (DUAL ? 2 : 1) * npc;

    const __nv_bfloat16* AH0 = aH + bz * sA;
    const __nv_bfloat16* AL0 = aL + bz * sA;
    const __nv_bfloat16* BH0 = bH + bz * sB;
    const __nv_bfloat16* BL0 = bL + bz * sB;
    const __nv_bfloat16* AH1 = DUAL ? a2H + bz * sA : nullptr;
    const __nv_bfloat16* AL1 = DUAL ? a2L + bz * sA : nullptr;
    const __nv_bfloat16* BH1 = DUAL ? b2H + bz * sB : nullptr;
    const __nv_bfloat16* BL1 = DUAL ? b2L + bz * sB : nullptr;

    // Per-thread fragment address constants (swizzle folded in; row&7 == lane&7).
    const uint32_t aRowB = (uint32_t)((wm * 64 + (lane & 15)) * 128);
    const uint32_t bRowB = (uint32_t)((wn * 32 + ((lane >> 4) << 3) + (lane & 7)) * 128);
    uint32_t gA16[2], gB16[2];
#pragma unroll
    for (int ks = 0; ks < 2; ++ks) {
        gA16[ks] = (uint32_t)(((ks * 2 + (lane >> 4)) ^ (lane & 7)) * 16);
        gB16[ks] = (uint32_t)(((ks * 2 + ((lane >> 3) & 1)) ^ (lane & 7)) * 16);
    }

    // prologue: chunks 0,1 -> stages 0,1 (all GEMMs here have nchunk >= 16)
    load_chunk(smem,           AH0, AL0, BH0, BL0, rowA, colB, lda, ldb, 0,  tid);
    load_chunk(smem + STAGE_B, AH0, AL0, BH0, BL0, rowA, colB, lda, ldb, BK, tid);

    for (int c = 0; c < nchunk; ++c) {
        if (c + 1 < nchunk)
            asm volatile("cp.async.wait_group 1;" ::: "memory");
        else
            asm volatile("cp.async.wait_group 0;" ::: "memory");
        __syncthreads();   // stage c%3 ready; all warps done with stage (c-1)%3

        if (c + 2 < nchunk) {
            int cn = c + 2;
            int p  = cn / npc;
            int k0 = (cn % npc) * BK;
            uint32_t dst = smem + (uint32_t)((cn % NSTAGE) * STAGE_B);
            if (!DUAL || p == 0)
                load_chunk(dst, AH0, AL0, BH0, BL0, rowA, colB, lda, ldb, k0, tid);
            else
                load_chunk(dst, AH1, AL1, BH1, BL1, rowA, colB, lda, ldb, k0, tid);
        }

        const uint32_t sA_ = smem + (uint32_t)((c % NSTAGE) * STAGE_B);
        const uint32_t sB_ = sA_ + TILE_B;

#pragma unroll
        for (int ks = 0; ks < 2; ++ks) {
            uint32_t bhf[4][2], blf[4][2];
#pragma unroll
            for (int np = 0; np < 2; ++np) {
                uint32_t boff = bRowB + (uint32_t)(np * 16 * 128);
                ldsm_x4(sB_ + boff + gB16[ks], bhf[2 * np][0], bhf[2 * np][1],
                                               bhf[2 * np + 1][0], bhf[2 * np + 1][1]);
                ldsm_x4(sB_ + (boff + gB16[ks] ^ 64u), blf[2 * np][0], blf[2 * np][1],
                                               blf[2 * np + 1][0], blf[2 * np + 1][1]);
            }
#pragma unroll
            for (int mf = 0; mf < 4; ++mf) {
                uint32_t aoff = aRowB + (uint32_t)(mf * 16 * 128);
                uint32_t ahf[4], alf[4];
                ldsm_x4(sA_ + aoff + gA16[ks], ahf[0], ahf[1], ahf[2], ahf[3]);
                if (THREE)
                    ldsm_x4(sA_ + (aoff + gA16[ks] ^ 64u), alf[0], alf[1], alf[2], alf[3]);
#pragma unroll
                for (int nf = 0; nf < 4; ++nf) {
                    mma16816(acc[mf][nf], ahf, bhf[nf]);      // hi*hi
                    mma16816(acc[mf][nf], ahf, blf[nf]);      // hi*lo
                    if (THREE)
                        mma16816(acc[mf][nf], alf, bhf[nf]);  // lo*hi
                }
            }
        }
    }

    // Epilogue: c0,c1 -> (row=rq, col=cq..cq+1); c2,c3 -> row+8.
    const int rq = lane >> 2, cq = (lane & 3) * 2;

#pragma unroll
    for (int mf = 0; mf < 4; ++mf) {
#pragma unroll
        for (int nf = 0; nf < 4; ++nf) {
            long col = colB + wn * 32 + nf * 8 + cq;
#pragma unroll
            for (int half = 0; half < 2; ++half) {
                long row = rowA + wm * 64 + mf * 16 + rq + half * 8;
                float v0 = acc[mf][nf][half * 2 + 0];
                float v1 = acc[mf][nf][half * 2 + 1];
                if (OUTF32) {
                    float* CF = cF + (long)bz * sC;
                    *(float2*)(CF + row * (long)ldc + col) = make_float2(v0, v1);
                } else {
                    if (TANH) { v0 = tanhf(v0); v1 = tanhf(v1); }
                    __nv_bfloat16 h0 = __float2bfloat16_rn(v0);
                    __nv_bfloat16 h1 = __float2bfloat16_rn(v1);
                    __nv_bfloat16 l0 = __float2bfloat16_rn(v0 - __bfloat162float(h0));
                    __nv_bfloat16 l1 = __float2bfloat16_rn(v1 - __bfloat162float(h1));
                    __nv_bfloat162 hp; hp.x = h0; hp.y = h1;
                    __nv_bfloat162 lp; lp.x = l0; lp.y = l1;
                    __nv_bfloat16* CH = cH + (long)bz * sC;
                    __nv_bfloat16* CL = cL + (long)bz * sC;
                    *(__nv_bfloat162*)(CH + row * (long)ldc + col) = hp;
                    *(__nv_bfloat162*)(CL + row * (long)ldc + col) = lp;
                }
            }
        }
    }
}

// ---------------------------------------------------------------------------
// fp32 -> (hi, lo) bf16 split helpers
// ---------------------------------------------------------------------------
__device__ __forceinline__ void split4(float4 v, uint2& uh, uint2& ul)
{
    float f[4] = {v.x, v.y, v.z, v.w};
    __nv_bfloat16 h[4], l[4];
#pragma unroll
    for (int j = 0; j < 4; ++j) {
        h[j] = __float2bfloat16_rn(f[j]);
        l[j] = __float2bfloat16_rn(f[j] - __bfloat162float(h[j]));
    }
    __nv_bfloat162 h01, h23, l01, l23;
    h01.x = h[0]; h01.y = h[1]; h23.x = h[2]; h23.y = h[3];
    l01.x = l[0]; l01.y = l[1]; l23.x = l[2]; l23.y = l[3];
    uh.x = *(uint32_t*)&h01; uh.y = *(uint32_t*)&h23;
    ul.x = *(uint32_t*)&l01; ul.y = *(uint32_t*)&l23;
}

__device__ __forceinline__ void split1(float f, __nv_bfloat16& h, __nv_bfloat16& l)
{
    h = __float2bfloat16_rn(f);
    l = __float2bfloat16_rn(f - __bfloat162float(h));
}

// Fused weight split: W1 (65536 f4) | Wout1 (131072 f4) | W2 (65536 f4)
__global__ void __launch_bounds__(256)
wsplit_kernel(const float4* __restrict__ w1, const float4* __restrict__ wo1,
              const float4* __restrict__ w2,
              uint2* __restrict__ w1h, uint2* __restrict__ w1l,
              uint2* __restrict__ wo1h, uint2* __restrict__ wo1l,
              uint2* __restrict__ w2h, uint2* __restrict__ w2l)
{
    long i = (long)blockIdx.x * blockDim.x + threadIdx.x;
    const float4* src; uint2 *dh, *dl; long j;
    if (i < 65536)       { src = w1;  dh = w1h;  dl = w1l;  j = i; }
    else if (i < 196608) { src = wo1; dh = wo1h; dl = wo1l; j = i - 65536; }
    else                 { src = w2;  dh = w2h;  dl = w2l;  j = i - 196608; }
    uint2 uh, ul;
    split4(src[j], uh, ul);
    dh[j] = uh; dl[j] = ul;
}

// ---------------------------------------------------------------------------
// Fused X split + transpose: reads X fp32 once, writes xh/xl (row-major) and
// xth/xtl (transposed). 32x32 tiles, block (32,8), grid (16,16,256).
// ---------------------------------------------------------------------------
__global__ void __launch_bounds__(256)
splitT_kernel(const float* __restrict__ X,
              __nv_bfloat16* __restrict__ xh, __nv_bfloat16* __restrict__ xl,
              __nv_bfloat16* __restrict__ xth, __nv_bfloat16* __restrict__ xtl)
{
    __shared__ float tile[32][33];
    const long base = (long)blockIdx.z * 262144;
    const int tx = threadIdx.x, ty = threadIdx.y;
    const int x = blockIdx.x * 32 + tx;
    const int y0 = blockIdx.y * 32;

#pragma unroll
    for (int j = 0; j < 32; j += 8) {
        long idx = base + (long)(y0 + ty + j) * 512 + x;
        float v = X[idx];
        tile[ty + j][tx] = v;
        __nv_bfloat16 h, l;
        split1(v, h, l);
        xh[idx] = h; xl[idx] = l;
    }
    __syncthreads();

    const int xo = blockIdx.y * 32 + tx;
    const int yo0 = blockIdx.x * 32;
#pragma unroll
    for (int j = 0; j < 32; j += 8) {
        long idx = base + (long)(yo0 + ty + j) * 512 + xo;
        float v = tile[tx][ty + j];
        __nv_bfloat16 h, l;
        split1(v, h, l);
        xth[idx] = h; xtl[idx] = l;
    }
}

// ---------------------------------------------------------------------------
// Row softmax over 512: fp32 in, hi/lo bf16 out (block 1 -- P feeds a GEMM).
// ---------------------------------------------------------------------------
__global__ void __launch_bounds__(128)
softmax512_f32(const float* __restrict__ S,
               __nv_bfloat16* __restrict__ PH, __nv_bfloat16* __restrict__ PL)
{
    __shared__ float redm[4], reds[4];
    const long row = blockIdx.x;
    const int t = threadIdx.x;

    float4 vv = ((const float4*)(S + row * 512))[t];
    float v[4] = {vv.x, vv.y, vv.z, vv.w};

    float m = fmaxf(fmaxf(v[0], v[1]), fmaxf(v[2], v[3]));
#pragma unroll
    for (int o = 16; o; o >>= 1) m = fmaxf(m, __shfl_xor_sync(0xffffffffu, m, o));
    if ((t & 31) == 0) redm[t >> 5] = m;
    __syncthreads();
    m = fmaxf(fmaxf(redm[0], redm[1]), fmaxf(redm[2], redm[3]));

    float s = 0.f;
#pragma unroll
    for (int j = 0; j < 4; ++j) { v[j] = __expf(v[j] - m); s += v[j]; }
#pragma unroll
    for (int o = 16; o; o >>= 1) s += __shfl_xor_sync(0xffffffffu, s, o);
    if ((t & 31) == 0) reds[t >> 5] = s;
    __syncthreads();
    s = reds[0] + reds[1] + reds[2] + reds[3];
    float r = 1.0f / s;

    float4 w = make_float4(v[0] * r, v[1] * r, v[2] * r, v[3] * r);
    uint2 uh, ul;
    split4(w, uh, ul);
    ((uint2*)(PH + row * 512))[t] = uh;
    ((uint2*)(PL + row * 512))[t] = ul;
}

// ---------------------------------------------------------------------------
// Block-2 fused softmax + column-sum (P2 never materialized).
// Grid (4, 256): block (rg, b) handles rows [rg*128, rg*128+128) of batch b.
// ---------------------------------------------------------------------------
__global__ void __launch_bounds__(256)
softmax_colmean_kernel(const float* __restrict__ S, float* __restrict__ pbar4)
{
    __shared__ float part[8][512];
    const int b = blockIdx.y, rg = blockIdx.x;
    const int wid = threadIdx.x >> 5, lane = threadIdx.x & 31;

    const float* Sb = S + (long)b * 262144 + (long)(rg * 128 + wid * 16) * 512;

    float csum[16];
#pragma unroll
    for (int j = 0; j < 16; ++j) csum[j] = 0.f;

    for (int r = 0; r < 16; ++r) {
        const float* row = Sb + (long)r * 512;
        float v[16];
#pragma unroll
        for (int j = 0; j < 16; ++j) v[j] = row[lane + 32 * j];
        float m = v[0];
#pragma unroll
        for (int j = 1; j < 16; ++j) m = fmaxf(m, v[j]);
#pragma unroll
        for (int o = 16; o; o >>= 1) m = fmaxf(m, __shfl_xor_sync(0xffffffffu, m, o));
        float s = 0.f;
#pragma unroll
        for (int j = 0; j < 16; ++j) { v[j] = __expf(v[j] - m); s += v[j]; }
#pragma unroll
        for (int o = 16; o; o >>= 1) s += __shfl_xor_sync(0xffffffffu, s, o);
        float inv = 1.0f / s;
#pragma unroll
        for (int j = 0; j < 16; ++j) csum[j] += v[j] * inv;
    }

#pragma unroll
    for (int j = 0; j < 16; ++j) part[wid][lane + 32 * j] = csum[j];
    __syncthreads();

#pragma unroll
    for (int cc = 0; cc < 2; ++cc) {
        int col = threadIdx.x + cc * 256;
        float s = 0.f;
#pragma unroll
        for (int w = 0; w < 8; ++w) s += part[w][col];
        pbar4[((long)rg * 256 + b) * 512 + col] = s;
    }
}

// ---------------------------------------------------------------------------
// qbar[b,j] = (1/512) * sum_i (hi+lo)(q2)[b,i,j]
// ---------------------------------------------------------------------------
__global__ void __launch_bounds__(512)
meanQ_kernel(const __nv_bfloat16* __restrict__ hi, const __nv_bfloat16* __restrict__ lo,
             float* __restrict__ qbar)
{
    const long base = (long)blockIdx.x * 262144 + threadIdx.x;
    float s = 0.f;
#pragma unroll 4
    for (int i = 0; i < 512; ++i) {
        long off = base + (long)i * 512;
        s += __bfloat162float(hi[off]) + __bfloat162float(lo[off]);
    }
    qbar[blockIdx.x * 512 + threadIdx.x] = s * (1.0f / 512.0f);
}

// ---------------------------------------------------------------------------
// Fused mixbar + final projection. One block per batch b (512 thr).
// ---------------------------------------------------------------------------
__global__ void __launch_bounds__(512)
mixfinal_kernel(const float* __restrict__ pbar4, const float* __restrict__ qbar,
                const __nv_bfloat16* __restrict__ hh, const __nv_bfloat16* __restrict__ hl,
                const float* __restrict__ W, float* __restrict__ out)
{
    __shared__ float pb[512], mb[512], qb[512];
    const int b = blockIdx.x, d = threadIdx.x;
    float p = 0.f;
#pragma unroll
    for (int rg = 0; rg < 4; ++rg)
        p += pbar4[((long)rg * 256 + b) * 512 + d];
    pb[d] = p * (1.0f / 512.0f);
    qb[d] = qbar[b * 512 + d];
    __syncthreads();

    const long base = (long)b * 262144 + d;
    float s = 0.f;
#pragma unroll 4
    for (int m = 0; m < 512; ++m) {
        long off = base + (long)m * 512;
        s += pb[m] * (__bfloat162float(hh[off]) + __bfloat162float(hl[off]));
    }
    mb[d] = s;
    __syncthreads();

    const float4* w4 = (const float4*)(W + (long)d * 1024);
    float o = 0.f;
#pragma unroll 4
    for (int c4 = 0; c4 < 128; ++c4) {
        float4 w = w4[c4];
        int c = c4 * 4;
        o += mb[c] * w.x + mb[c + 1] * w.y + mb[c + 2] * w.z + mb[c + 3] * w.w;
    }
#pragma unroll 4
    for (int c4 = 128; c4 < 256; ++c4) {
        float4 w = w4[c4];
        int c = c4 * 4 - 512;
        o += qb[c] * w.x + qb[c + 1] * w.y + qb[c + 2] * w.z + qb[c + 3] * w.w;
    }
    out[b * 512 + d] = o;
}

// ---------------------------------------------------------------------------

extern "C" void kernel_launch(void* const* d_in, const int* in_sizes, int n_in,
                              void* d_out, int out_size)
{
    const float* x     = (const float*)d_in[0];
    const float* Win1  = (const float*)d_in[1];
    const float* Wout1 = (const float*)d_in[2];
    const float* Win2  = (const float*)d_in[3];
    const float* Wout2 = (const float*)d_in[4];
    float* out = (float*)d_out;

    __nv_bfloat16 *xh, *xl, *xth, *xtl, *qh, *ql, *sh, *sl, *mh, *ml;
    __nv_bfloat16 *w1h, *w1l, *wo1h, *wo1l, *w2h, *w2l;
    float *sf, *pbar4, *qbar;
    cudaGetSymbolAddress((void**)&xh,  g_xh);   cudaGetSymbolAddress((void**)&xl,  g_xl);
    cudaGetSymbolAddress((void**)&xth, g_xth);  cudaGetSymbolAddress((void**)&xtl, g_xtl);
    cudaGetSymbolAddress((void**)&qh,  g_qh);   cudaGetSymbolAddress((void**)&ql,  g_ql);
    cudaGetSymbolAddress((void**)&sh,  g_sh);   cudaGetSymbolAddress((void**)&sl,  g_sl);
    cudaGetSymbolAddress((void**)&mh,  g_mh);   cudaGetSymbolAddress((void**)&ml,  g_ml);
    cudaGetSymbolAddress((void**)&sf,  g_sf);
    cudaGetSymbolAddress((void**)&w1h, g_w1h);  cudaGetSymbolAddress((void**)&w1l, g_w1l);
    cudaGetSymbolAddress((void**)&wo1h,g_wo1h); cudaGetSymbolAddress((void**)&wo1l,g_wo1l);
    cudaGetSymbolAddress((void**)&w2h, g_w2h);  cudaGetSymbolAddress((void**)&w2l, g_w2l);
    cudaGetSymbolAddress((void**)&pbar4, g_pbar4);
    cudaGetSymbolAddress((void**)&qbar,  g_qbar);

    cudaFuncSetAttribute(gemm_hmma<false, false, false, true>,
                         cudaFuncAttributeMaxDynamicSharedMemorySize, GEMM_DYN_SMEM);
    cudaFuncSetAttribute(gemm_hmma<false, false, true, true>,
                         cudaFuncAttributeMaxDynamicSharedMemorySize, GEMM_DYN_SMEM);
    cudaFuncSetAttribute(gemm_hmma<true, true, false, true>,
                         cudaFuncAttributeMaxDynamicSharedMemorySize, GEMM_DYN_SMEM);
    cudaFuncSetAttribute(gemm_hmma<false, false, false, false>,
                         cudaFuncAttributeMaxDynamicSharedMemorySize, GEMM_DYN_SMEM);
    cudaFuncSetAttribute(gemm_hmma<false, false, true, false>,
                         cudaFuncAttributeMaxDynamicSharedMemorySize, GEMM_DYN_SMEM);

    const int  M_FLAT = BATCH * SEQ;     // 131072
    const long LDb = 262144;

    // ---- splits (X split fused with transpose) ----
    wsplit_kernel<<<262144 / 256, 256>>>(
        (const float4*)Win1, (const float4*)Wout1, (const float4*)Win2,
        (uint2*)w1h, (uint2*)w1l, (uint2*)wo1h, (uint2*)wo1l, (uint2*)w2h, (uint2*)w2l);
    splitT_kernel<<<dim3(16, 16, 256), dim3(32, 8)>>>(x, xh, xl, xth, xtl);

    // ---- block 1 (full 3-pass: errors flow unpooled through h) ----
    // q1 = X @ Win1^T
    gemm_hmma<false, false, false, true><<<dim3(4, 1024, 1), 256, GEMM_DYN_SMEM>>>(
        xh, xl, 512, 0, w1h, w1l, 512, 0,
        nullptr, nullptr, nullptr, nullptr, qh, ql, nullptr, 512, 0, 512);
    // S1[b] = q1[b] @ X[b]^T  (fp32 out)
    gemm_hmma<false, false, true, true><<<dim3(4, 4, 256), 256, GEMM_DYN_SMEM>>>(
        qh, ql, 512, LDb, xh, xl, 512, LDb,
        nullptr, nullptr, nullptr, nullptr, nullptr, nullptr, sf, 512, LDb, 512);
    softmax512_f32<<<M_FLAT, 128>>>(sf, sh, sl);
    // mix1[b] = P1[b] @ X[b]   (B = X^T, K-major over m)
    gemm_hmma<false, false, false, true><<<dim3(4, 4, 256), 256, GEMM_DYN_SMEM>>>(
        sh, sl, 512, LDb, xth, xtl, 512, LDb,
        nullptr, nullptr, nullptr, nullptr, mh, ml, nullptr, 512, LDb, 512);
    // h = tanh(mix1 @ Wout1[:, :512]^T + q1 @ Wout1[:, 512:]^T) -> overwrite X slots
    gemm_hmma<true, true, false, true><<<dim3(4, 1024, 1), 256, GEMM_DYN_SMEM>>>(
        mh, ml, 512, 0, wo1h, wo1l, 1024, 0,
        qh, ql, wo1h + 512, wo1l + 512, xh, xl, nullptr, 512, 0, 512);

    // ---- block 2 (2-pass GEMMs: mean-pool over L suppresses their error) ----
    // q2 = h @ Win2^T
    gemm_hmma<false, false, false, false><<<dim3(4, 1024, 1), 256, GEMM_DYN_SMEM>>>(
        xh, xl, 512, 0, w2h, w2l, 512, 0,
        nullptr, nullptr, nullptr, nullptr, qh, ql, nullptr, 512, 0, 512);
    // S2[b] = q2[b] @ h[b]^T  (fp32 out)
    gemm_hmma<false, false, true, false><<<dim3(4, 4, 256), 256, GEMM_DYN_SMEM>>>(
        qh, ql, 512, LDb, xh, xl, 512, LDb,
        nullptr, nullptr, nullptr, nullptr, nullptr, nullptr, sf, 512, LDb, 512);

    // ---- fused tail: softmax(S2) column means without materializing P2 ----
    softmax_colmean_kernel<<<dim3(4, 256), 256>>>(sf, pbar4);
    meanQ_kernel<<<BATCH, 512>>>(qh, ql, qbar);
    mixfinal_kernel<<<BATCH, 512>>>(pbar4, qbar, xh, xl, Wout2, out);
}

// round 16
// speedup vs baseline: 1.1408x; 1.0356x over previous
#include <cuda_runtime.h>
#include <cuda_bf16.h>
#include <math.h>
#include <stdint.h>

#define BATCH 256
#define SEQ   512
#define DIM   512

static const long NEL = (long)BATCH * SEQ * DIM;  // 67108864

// ---------------------------------------------------------------------------
// Scratch: __device__ globals (allocation-free rule)
// ---------------------------------------------------------------------------
static __device__ __nv_bfloat16 g_xh[67108864], g_xl[67108864];   // X / later h
static __device__ __nv_bfloat16 g_xth[67108864], g_xtl[67108864]; // X^T (block 1)
static __device__ __nv_bfloat16 g_qh[67108864], g_ql[67108864];   // q1 / q2
static __device__ __nv_bfloat16 g_sh[67108864], g_sl[67108864];   // P1 hi/lo
static __device__ __nv_bfloat16 g_mh[67108864], g_ml[67108864];   // mix1
static __device__ float g_sf[67108864];                           // scores fp32
static __device__ __nv_bfloat16 g_w1h[262144], g_w1l[262144];
static __device__ __nv_bfloat16 g_wo1h[524288], g_wo1l[524288];
static __device__ __nv_bfloat16 g_w2h[262144], g_w2l[262144];
static __device__ float g_pbar4[524288];   // [4][256][512] P2 col-sum partials
static __device__ float g_qbar4[524288];   // [4][256][512] q2 col-sum partials

// ---------------------------------------------------------------------------
// PTX helpers (sm_80+ baseline: cp.async / ldmatrix / mma.sync bf16)
// ---------------------------------------------------------------------------
__device__ __forceinline__ void cp_async16(uint32_t s, const void* g) {
    asm volatile("cp.async.cg.shared.global [%0], [%1], 16;"
                 :: "r"(s), "l"(__cvta_generic_to_global(g)) : "memory");
}

__device__ __forceinline__ void ldsm_x4(uint32_t addr, uint32_t& r0, uint32_t& r1,
                                        uint32_t& r2, uint32_t& r3) {
    asm volatile("ldmatrix.sync.aligned.m8n8.x4.shared.b16 {%0,%1,%2,%3}, [%4];"
                 : "=r"(r0), "=r"(r1), "=r"(r2), "=r"(r3) : "r"(addr));
}

__device__ __forceinline__ void mma16816(float* c, const uint32_t* a, const uint32_t* b) {
    asm volatile("mma.sync.aligned.m16n8k16.row.col.f32.bf16.bf16.f32 "
                 "{%0,%1,%2,%3}, {%4,%5,%6,%7}, {%8,%9}, {%0,%1,%2,%3};"
                 : "+f"(c[0]), "+f"(c[1]), "+f"(c[2]), "+f"(c[3])
                 : "r"(a[0]), "r"(a[1]), "r"(a[2]), "r"(a[3]), "r"(b[0]), "r"(b[1]));
}

// ---------------------------------------------------------------------------
// Split-bf16 HMMA GEMM (R10-proven mainloop).
//   C[m,n] = sum_k A[m,k]*B[n,k], A=aH+aL, B=bH+bL.
//   THREE=1: AH*BH + AH*BL + AL*BH  (full 3-pass)
//   THREE=0: AH*BH + AH*BL          (2-pass; q2/S2 only -- pooled error)
//   QSUM=1:  epilogue also emits per-block fp32 column sums (for qbar) and
//            skips the cL write (ql is dead when S2 is 2-pass).
// ---------------------------------------------------------------------------
#define BK      32
#define TILE_B  (128 * 128)           // 16384 B: one operand (hi+lo packed)
#define STAGE_B (2 * TILE_B)          // A, B
#define NSTAGE  3
#define GEMM_DYN_SMEM (NSTAGE * STAGE_B)   // 98304 B

// granule g (16B) at row r -> g ^ (r&7) within the 128B row
__device__ __forceinline__ void load_chunk(uint32_t sbase,
    const __nv_bfloat16* pAH, const __nv_bfloat16* pAL,
    const __nv_bfloat16* pBH, const __nv_bfloat16* pBL,
    long rowA, long colB, int lda, int ldb, int k0, int tid)
{
#pragma unroll
    for (int i = 0; i < 8; ++i) {
        int seg = tid + i * 256;            // 0..2047 16B segments
        int t   = seg >> 10;                // 0=A, 1=B
        int r   = (seg >> 3) & 127;         // row 0..127
        int g   = seg & 7;                  // granule 0..7 (0-3 hi, 4-7 lo)
        int c16 = g & 3;
        const __nv_bfloat16* src =
            (t ? ((g & 4) ? pBL : pBH) : ((g & 4) ? pAL : pAH));
        long row0 = t ? colB : rowA;
        int  ld   = t ? ldb  : lda;
        cp_async16(sbase + (uint32_t)(t * TILE_B + r * 128 + ((g ^ (r & 7)) * 16)),
                   src + (row0 + r) * (long)ld + k0 + c16 * 8);
    }
    asm volatile("cp.async.commit_group;" ::: "memory");
}

template<bool DUAL, bool TANH, bool OUTF32, bool THREE, bool QSUM>
__global__ void __launch_bounds__(256, 2)
gemm_hmma(const __nv_bfloat16* __restrict__ aH, const __nv_bfloat16* __restrict__ aL,
          int lda, long sA,
          const __nv_bfloat16* __restrict__ bH, const __nv_bfloat16* __restrict__ bL,
          int ldb, long sB,
          const __nv_bfloat16* __restrict__ a2H, const __nv_bfloat16* __restrict__ a2L,
          const __nv_bfloat16* __restrict__ b2H, const __nv_bfloat16* __restrict__ b2L,
          __nv_bfloat16* __restrict__ cH, __nv_bfloat16* __restrict__ cL,
          float* __restrict__ cF,
          int ldc, long sC, int K)
{
    extern __shared__ char smem_raw[];
    const uint32_t smem = (uint32_t)__cvta_generic_to_shared(smem_raw);
    __shared__ float cs[2][128];   // QSUM cross-warp column partials

    const int tid  = threadIdx.x;
    const int lane = tid & 31;
    const int wid  = tid >> 5;
    const int wm   = wid & 1;       // 2 m-groups of 64
    const int wn   = wid >> 1;      // 4 n-groups of 32
    const int bz   = blockIdx.z;
    const long rowA = (long)blockIdx.y * 128;
    const long colB = (long)blockIdx.x * 128;

    float acc[4][4][4];
#pragma unroll
    for (int i = 0; i < 4; ++i)
#pragma unroll
        for (int j = 0; j < 4; ++j)
#pragma unroll
            for (int k = 0; k < 4; ++k) acc[i][j][k] = 0.f;

    const int npc    = K / BK;                 // chunks per pair
    const int nchunk = (DUAL ? 2 : 1) * npc;

    const __nv_bfloat16* AH0 = aH + bz * sA;
    const __nv_bfloat16* AL0 = aL + bz * sA;
    const __nv_bfloat16* BH0 = bH + bz * sB;
    const __nv_bfloat16* BL0 = bL + bz * sB;
    const __nv_bfloat16* AH1 = DUAL ? a2H + bz * sA : nullptr;
    const __nv_bfloat16* AL1 = DUAL ? a2L + bz * sA : nullptr;
    const __nv_bfloat16* BH1 = DUAL ? b2H + bz * sB : nullptr;
    const __nv_bfloat16* BL1 = DUAL ? b2L + bz * sB : nullptr;

    // Per-thread fragment address constants (swizzle folded in; row&7 == lane&7).
    const uint32_t aRowB = (uint32_t)((wm * 64 + (lane & 15)) * 128);
    const uint32_t bRowB = (uint32_t)((wn * 32 + ((lane >> 4) << 3) + (lane & 7)) * 128);
    uint32_t gA16[2], gB16[2];
#pragma unroll
    for (int ks = 0; ks < 2; ++ks) {
        gA16[ks] = (uint32_t)(((ks * 2 + (lane >> 4)) ^ (lane & 7)) * 16);
        gB16[ks] = (uint32_t)(((ks * 2 + ((lane >> 3) & 1)) ^ (lane & 7)) * 16);
    }

    // prologue: chunks 0,1 -> stages 0,1 (all GEMMs here have nchunk >= 16)
    load_chunk(smem,           AH0, AL0, BH0, BL0, rowA, colB, lda, ldb, 0,  tid);
    load_chunk(smem + STAGE_B, AH0, AL0, BH0, BL0, rowA, colB, lda, ldb, BK, tid);

    for (int c = 0; c < nchunk; ++c) {
        if (c + 1 < nchunk)
            asm volatile("cp.async.wait_group 1;" ::: "memory");
        else
            asm volatile("cp.async.wait_group 0;" ::: "memory");
        __syncthreads();   // stage c%3 ready; all warps done with stage (c-1)%3

        if (c + 2 < nchunk) {
            int cn = c + 2;
            int p  = cn / npc;
            int k0 = (cn % npc) * BK;
            uint32_t dst = smem + (uint32_t)((cn % NSTAGE) * STAGE_B);
            if (!DUAL || p == 0)
                load_chunk(dst, AH0, AL0, BH0, BL0, rowA, colB, lda, ldb, k0, tid);
            else
                load_chunk(dst, AH1, AL1, BH1, BL1, rowA, colB, lda, ldb, k0, tid);
        }

        const uint32_t sA_ = smem + (uint32_t)((c % NSTAGE) * STAGE_B);
        const uint32_t sB_ = sA_ + TILE_B;

#pragma unroll
        for (int ks = 0; ks < 2; ++ks) {
            uint32_t bhf[4][2], blf[4][2];
#pragma unroll
            for (int np = 0; np < 2; ++np) {
                uint32_t boff = bRowB + (uint32_t)(np * 16 * 128);
                ldsm_x4(sB_ + boff + gB16[ks], bhf[2 * np][0], bhf[2 * np][1],
                                               bhf[2 * np + 1][0], bhf[2 * np + 1][1]);
                ldsm_x4(sB_ + (boff + gB16[ks] ^ 64u), blf[2 * np][0], blf[2 * np][1],
                                               blf[2 * np + 1][0], blf[2 * np + 1][1]);
            }
#pragma unroll
            for (int mf = 0; mf < 4; ++mf) {
                uint32_t aoff = aRowB + (uint32_t)(mf * 16 * 128);
                uint32_t ahf[4], alf[4];
                ldsm_x4(sA_ + aoff + gA16[ks], ahf[0], ahf[1], ahf[2], ahf[3]);
                if (THREE)
                    ldsm_x4(sA_ + (aoff + gA16[ks] ^ 64u), alf[0], alf[1], alf[2], alf[3]);
#pragma unroll
                for (int nf = 0; nf < 4; ++nf) {
                    mma16816(acc[mf][nf], ahf, bhf[nf]);      // hi*hi
                    mma16816(acc[mf][nf], ahf, blf[nf]);      // hi*lo
                    if (THREE)
                        mma16816(acc[mf][nf], alf, bhf[nf]);  // lo*hi
                }
            }
        }
    }

    // Epilogue: c0,c1 -> (row=rq, col=cq..cq+1); c2,c3 -> row+8.
    const int rq = lane >> 2, cq = (lane & 3) * 2;

#pragma unroll
    for (int mf = 0; mf < 4; ++mf) {
#pragma unroll
        for (int nf = 0; nf < 4; ++nf) {
            long col = colB + wn * 32 + nf * 8 + cq;
#pragma unroll
            for (int half = 0; half < 2; ++half) {
                long row = rowA + wm * 64 + mf * 16 + rq + half * 8;
                float v0 = acc[mf][nf][half * 2 + 0];
                float v1 = acc[mf][nf][half * 2 + 1];
                if (OUTF32) {
                    float* CF = cF + (long)bz * sC;
                    *(float2*)(CF + row * (long)ldc + col) = make_float2(v0, v1);
                } else if (QSUM) {
                    // hi only; lo is dead (S2 2-pass never reads A-lo)
                    __nv_bfloat162 hp;
                    hp.x = __float2bfloat16_rn(v0);
                    hp.y = __float2bfloat16_rn(v1);
                    *(__nv_bfloat162*)(cH + row * (long)ldc + col) = hp;
                } else {
                    if (TANH) { v0 = tanhf(v0); v1 = tanhf(v1); }
                    __nv_bfloat16 h0 = __float2bfloat16_rn(v0);
                    __nv_bfloat16 h1 = __float2bfloat16_rn(v1);
                    __nv_bfloat16 l0 = __float2bfloat16_rn(v0 - __bfloat162float(h0));
                    __nv_bfloat16 l1 = __float2bfloat16_rn(v1 - __bfloat162float(h1));
                    __nv_bfloat162 hp; hp.x = h0; hp.y = h1;
                    __nv_bfloat162 lp; lp.x = l0; lp.y = l1;
                    __nv_bfloat16* CH = cH + (long)bz * sC;
                    __nv_bfloat16* CL = cL + (long)bz * sC;
                    *(__nv_bfloat162*)(CH + row * (long)ldc + col) = hp;
                    *(__nv_bfloat162*)(CL + row * (long)ldc + col) = lp;
                }
            }
        }
    }

    if (QSUM) {
        // Per-block fp32 column sums (deterministic, no atomics).
        // Thread-local: sum each of its 8 columns over its 8 rows.
        float cl[4][2];
#pragma unroll
        for (int nf = 0; nf < 4; ++nf)
#pragma unroll
            for (int j = 0; j < 2; ++j) {
                float s = 0.f;
#pragma unroll
                for (int mf = 0; mf < 4; ++mf)
                    s += acc[mf][nf][j] + acc[mf][nf][2 + j];
                cl[nf][j] = s;
            }
        // warp reduce over rq (lane bits 2..4) -> warp's 64-row column sums
#pragma unroll
        for (int off = 4; off <= 16; off <<= 1)
#pragma unroll
            for (int nf = 0; nf < 4; ++nf)
#pragma unroll
                for (int j = 0; j < 2; ++j)
                    cl[nf][j] += __shfl_xor_sync(0xffffffffu, cl[nf][j], off);
        if (lane < 4) {
#pragma unroll
            for (int nf = 0; nf < 4; ++nf)
#pragma unroll
                for (int j = 0; j < 2; ++j)
                    cs[wm][wn * 32 + nf * 8 + lane * 2 + j] = cl[nf][j];
        }
        __syncthreads();
        if (tid < 128) {
            const int sub = (int)(blockIdx.y & 3);
            const int b   = (int)(blockIdx.y >> 2);
            cF[((long)sub * 256 + b) * 512 + colB + tid] = cs[0][tid] + cs[1][tid];
        }
    }
}

// ---------------------------------------------------------------------------
// fp32 -> (hi, lo) bf16 split helpers
// ---------------------------------------------------------------------------
__device__ __forceinline__ void split4(float4 v, uint2& uh, uint2& ul)
{
    float f[4] = {v.x, v.y, v.z, v.w};
    __nv_bfloat16 h[4], l[4];
#pragma unroll
    for (int j = 0; j < 4; ++j) {
        h[j] = __float2bfloat16_rn(f[j]);
        l[j] = __float2bfloat16_rn(f[j] - __bfloat162float(h[j]));
    }
    __nv_bfloat162 h01, h23, l01, l23;
    h01.x = h[0]; h01.y = h[1]; h23.x = h[2]; h23.y = h[3];
    l01.x = l[0]; l01.y = l[1]; l23.x = l[2]; l23.y = l[3];
    uh.x = *(uint32_t*)&h01; uh.y = *(uint32_t*)&h23;
    ul.x = *(uint32_t*)&l01; ul.y = *(uint32_t*)&l23;
}

__device__ __forceinline__ void split1(float f, __nv_bfloat16& h, __nv_bfloat16& l)
{
    h = __float2bfloat16_rn(f);
    l = __float2bfloat16_rn(f - __bfloat162float(h));
}

// Fused weight split: W1 (65536 f4) | Wout1 (131072 f4) | W2 (65536 f4)
__global__ void __launch_bounds__(256)
wsplit_kernel(const float4* __restrict__ w1, const float4* __restrict__ wo1,
              const float4* __restrict__ w2,
              uint2* __restrict__ w1h, uint2* __restrict__ w1l,
              uint2* __restrict__ wo1h, uint2* __restrict__ wo1l,
              uint2* __restrict__ w2h, uint2* __restrict__ w2l)
{
    long i = (long)blockIdx.x * blockDim.x + threadIdx.x;
    const float4* src; uint2 *dh, *dl; long j;
    if (i < 65536)       { src = w1;  dh = w1h;  dl = w1l;  j = i; }
    else if (i < 196608) { src = wo1; dh = wo1h; dl = wo1l; j = i - 65536; }
    else                 { src = w2;  dh = w2h;  dl = w2l;  j = i - 196608; }
    uint2 uh, ul;
    split4(src[j], uh, ul);
    dh[j] = uh; dl[j] = ul;
}

// ---------------------------------------------------------------------------
// Fused X split + transpose: reads X fp32 once, writes xh/xl (row-major) and
// xth/xtl (transposed). 32x32 tiles, block (32,8), grid (16,16,256).
// ---------------------------------------------------------------------------
__global__ void __launch_bounds__(256)
splitT_kernel(const float* __restrict__ X,
              __nv_bfloat16* __restrict__ xh, __nv_bfloat16* __restrict__ xl,
              __nv_bfloat16* __restrict__ xth, __nv_bfloat16* __restrict__ xtl)
{
    __shared__ float tile[32][33];
    const long base = (long)blockIdx.z * 262144;
    const int tx = threadIdx.x, ty = threadIdx.y;
    const int x = blockIdx.x * 32 + tx;
    const int y0 = blockIdx.y * 32;

#pragma unroll
    for (int j = 0; j < 32; j += 8) {
        long idx = base + (long)(y0 + ty + j) * 512 + x;
        float v = X[idx];
        tile[ty + j][tx] = v;
        __nv_bfloat16 h, l;
        split1(v, h, l);
        xh[idx] = h; xl[idx] = l;
    }
    __syncthreads();

    const int xo = blockIdx.y * 32 + tx;
    const int yo0 = blockIdx.x * 32;
#pragma unroll
    for (int j = 0; j < 32; j += 8) {
        long idx = base + (long)(yo0 + ty + j) * 512 + xo;
        float v = tile[tx][ty + j];
        __nv_bfloat16 h, l;
        split1(v, h, l);
        xth[idx] = h; xtl[idx] = l;
    }
}

// ---------------------------------------------------------------------------
// Row softmax over 512: fp32 in, hi/lo bf16 out (block 1 -- P feeds a GEMM).
// ---------------------------------------------------------------------------
__global__ void __launch_bounds__(128)
softmax512_f32(const float* __restrict__ S,
               __nv_bfloat16* __restrict__ PH, __nv_bfloat16* __restrict__ PL)
{
    __shared__ float redm[4], reds[4];
    const long row = blockIdx.x;
    const int t = threadIdx.x;

    float4 vv = ((const float4*)(S + row * 512))[t];
    float v[4] = {vv.x, vv.y, vv.z, vv.w};

    float m = fmaxf(fmaxf(v[0], v[1]), fmaxf(v[2], v[3]));
#pragma unroll
    for (int o = 16; o; o >>= 1) m = fmaxf(m, __shfl_xor_sync(0xffffffffu, m, o));
    if ((t & 31) == 0) redm[t >> 5] = m;
    __syncthreads();
    m = fmaxf(fmaxf(redm[0], redm[1]), fmaxf(redm[2], redm[3]));

    float s = 0.f;
#pragma unroll
    for (int j = 0; j < 4; ++j) { v[j] = __expf(v[j] - m); s += v[j]; }
#pragma unroll
    for (int o = 16; o; o >>= 1) s += __shfl_xor_sync(0xffffffffu, s, o);
    if ((t & 31) == 0) reds[t >> 5] = s;
    __syncthreads();
    s = reds[0] + reds[1] + reds[2] + reds[3];
    float r = 1.0f / s;

    float4 w = make_float4(v[0] * r, v[1] * r, v[2] * r, v[3] * r);
    uint2 uh, ul;
    split4(w, uh, ul);
    ((uint2*)(PH + row * 512))[t] = uh;
    ((uint2*)(PL + row * 512))[t] = ul;
}

// ---------------------------------------------------------------------------
// Block-2 fused softmax + column-sum (P2 never materialized).
// Grid (4, 256): block (rg, b) handles rows [rg*128, rg*128+128) of batch b.
// ---------------------------------------------------------------------------
__global__ void __launch_bounds__(256)
softmax_colmean_kernel(const float* __restrict__ S, float* __restrict__ pbar4)
{
    __shared__ float part[8][512];
    const int b = blockIdx.y, rg = blockIdx.x;
    const int wid = threadIdx.x >> 5, lane = threadIdx.x & 31;

    const float* Sb = S + (long)b * 262144 + (long)(rg * 128 + wid * 16) * 512;

    float csum[16];
#pragma unroll
    for (int j = 0; j < 16; ++j) csum[j] = 0.f;

    for (int r = 0; r < 16; ++r) {
        const float* row = Sb + (long)r * 512;
        float v[16];
#pragma unroll
        for (int j = 0; j < 16; ++j) v[j] = row[lane + 32 * j];
        float m = v[0];
#pragma unroll
        for (int j = 1; j < 16; ++j) m = fmaxf(m, v[j]);
#pragma unroll
        for (int o = 16; o; o >>= 1) m = fmaxf(m, __shfl_xor_sync(0xffffffffu, m, o));
        float s = 0.f;
#pragma unroll
        for (int j = 0; j < 16; ++j) { v[j] = __expf(v[j] - m); s += v[j]; }
#pragma unroll
        for (int o = 16; o; o >>= 1) s += __shfl_xor_sync(0xffffffffu, s, o);
        float inv = 1.0f / s;
#pragma unroll
        for (int j = 0; j < 16; ++j) csum[j] += v[j] * inv;
    }

#pragma unroll
    for (int j = 0; j < 16; ++j) part[wid][lane + 32 * j] = csum[j];
    __syncthreads();

#pragma unroll
    for (int cc = 0; cc < 2; ++cc) {
        int col = threadIdx.x + cc * 256;
        float s = 0.f;
#pragma unroll
        for (int w = 0; w < 8; ++w) s += part[w][col];
        pbar4[((long)rg * 256 + b) * 512 + col] = s;
    }
}

// ---------------------------------------------------------------------------
// Fused mixbar + final projection. One block per batch b (512 thr).
//   pb[d] = (1/512) * sum_rg pbar4[rg][b][d]
//   qb[d] = (1/512) * sum_rg qbar4[rg][b][d]
//   mb[d] = sum_m pb[m] * (hh+hl)[b,m,d]
//   out[b,d] = sum_c mb[c]*W[d,c] + sum_c qb[c]*W[d,512+c]
// ---------------------------------------------------------------------------
__global__ void __launch_bounds__(512)
mixfinal_kernel(const float* __restrict__ pbar4, const float* __restrict__ qbar4,
                const __nv_bfloat16* __restrict__ hh, const __nv_bfloat16* __restrict__ hl,
                const float* __restrict__ W, float* __restrict__ out)
{
    __shared__ float pb[512], mb[512], qb[512];
    const int b = blockIdx.x, d = threadIdx.x;
    float p = 0.f, q = 0.f;
#pragma unroll
    for (int rg = 0; rg < 4; ++rg) {
        p += pbar4[((long)rg * 256 + b) * 512 + d];
        q += qbar4[((long)rg * 256 + b) * 512 + d];
    }
    pb[d] = p * (1.0f / 512.0f);
    qb[d] = q * (1.0f / 512.0f);
    __syncthreads();

    const long base = (long)b * 262144 + d;
    float s = 0.f;
#pragma unroll 4
    for (int m = 0; m < 512; ++m) {
        long off = base + (long)m * 512;
        s += pb[m] * (__bfloat162float(hh[off]) + __bfloat162float(hl[off]));
    }
    mb[d] = s;
    __syncthreads();

    const float4* w4 = (const float4*)(W + (long)d * 1024);
    float o = 0.f;
#pragma unroll 4
    for (int c4 = 0; c4 < 128; ++c4) {
        float4 w = w4[c4];
        int c = c4 * 4;
        o += mb[c] * w.x + mb[c + 1] * w.y + mb[c + 2] * w.z + mb[c + 3] * w.w;
    }
#pragma unroll 4
    for (int c4 = 128; c4 < 256; ++c4) {
        float4 w = w4[c4];
        int c = c4 * 4 - 512;
        o += qb[c] * w.x + qb[c + 1] * w.y + qb[c + 2] * w.z + qb[c + 3] * w.w;
    }
    out[b * 512 + d] = o;
}

// ---------------------------------------------------------------------------

extern "C" void kernel_launch(void* const* d_in, const int* in_sizes, int n_in,
                              void* d_out, int out_size)
{
    const float* x     = (const float*)d_in[0];
    const float* Win1  = (const float*)d_in[1];
    const float* Wout1 = (const float*)d_in[2];
    const float* Win2  = (const float*)d_in[3];
    const float* Wout2 = (const float*)d_in[4];
    float* out = (float*)d_out;

    __nv_bfloat16 *xh, *xl, *xth, *xtl, *qh, *ql, *sh, *sl, *mh, *ml;
    __nv_bfloat16 *w1h, *w1l, *wo1h, *wo1l, *w2h, *w2l;
    float *sf, *pbar4, *qbar4;
    cudaGetSymbolAddress((void**)&xh,  g_xh);   cudaGetSymbolAddress((void**)&xl,  g_xl);
    cudaGetSymbolAddress((void**)&xth, g_xth);  cudaGetSymbolAddress((void**)&xtl, g_xtl);
    cudaGetSymbolAddress((void**)&qh,  g_qh);   cudaGetSymbolAddress((void**)&ql,  g_ql);
    cudaGetSymbolAddress((void**)&sh,  g_sh);   cudaGetSymbolAddress((void**)&sl,  g_sl);
    cudaGetSymbolAddress((void**)&mh,  g_mh);   cudaGetSymbolAddress((void**)&ml,  g_ml);
    cudaGetSymbolAddress((void**)&sf,  g_sf);
    cudaGetSymbolAddress((void**)&w1h, g_w1h);  cudaGetSymbolAddress((void**)&w1l, g_w1l);
    cudaGetSymbolAddress((void**)&wo1h,g_wo1h); cudaGetSymbolAddress((void**)&wo1l,g_wo1l);
    cudaGetSymbolAddress((void**)&w2h, g_w2h);  cudaGetSymbolAddress((void**)&w2l, g_w2l);
    cudaGetSymbolAddress((void**)&pbar4, g_pbar4);
    cudaGetSymbolAddress((void**)&qbar4, g_qbar4);

    cudaFuncSetAttribute(gemm_hmma<false, false, false, true, false>,
                         cudaFuncAttributeMaxDynamicSharedMemorySize, GEMM_DYN_SMEM);
    cudaFuncSetAttribute(gemm_hmma<false, false, true, true, false>,
                         cudaFuncAttributeMaxDynamicSharedMemorySize, GEMM_DYN_SMEM);
    cudaFuncSetAttribute(gemm_hmma<true, true, false, true, false>,
                         cudaFuncAttributeMaxDynamicSharedMemorySize, GEMM_DYN_SMEM);
    cudaFuncSetAttribute(gemm_hmma<false, false, false, false, true>,
                         cudaFuncAttributeMaxDynamicSharedMemorySize, GEMM_DYN_SMEM);
    cudaFuncSetAttribute(gemm_hmma<false, false, true, false, false>,
                         cudaFuncAttributeMaxDynamicSharedMemorySize, GEMM_DYN_SMEM);

    const int  M_FLAT = BATCH * SEQ;     // 131072
    const long LDb = 262144;

    // ---- splits (X split fused with transpose) ----
    wsplit_kernel<<<262144 / 256, 256>>>(
        (const float4*)Win1, (const float4*)Wout1, (const float4*)Win2,
        (uint2*)w1h, (uint2*)w1l, (uint2*)wo1h, (uint2*)wo1l, (uint2*)w2h, (uint2*)w2l);
    splitT_kernel<<<dim3(16, 16, 256), dim3(32, 8)>>>(x, xh, xl, xth, xtl);

    // ---- block 1 (full 3-pass: errors flow unpooled through h) ----
    // q1 = X @ Win1^T
    gemm_hmma<false, false, false, true, false><<<dim3(4, 1024, 1), 256, GEMM_DYN_SMEM>>>(
        xh, xl, 512, 0, w1h, w1l, 512, 0,
        nullptr, nullptr, nullptr, nullptr, qh, ql, nullptr, 512, 0, 512);
    // S1[b] = q1[b] @ X[b]^T  (fp32 out)
    gemm_hmma<false, false, true, true, false><<<dim3(4, 4, 256), 256, GEMM_DYN_SMEM>>>(
        qh, ql, 512, LDb, xh, xl, 512, LDb,
        nullptr, nullptr, nullptr, nullptr, nullptr, nullptr, sf, 512, LDb, 512);
    softmax512_f32<<<M_FLAT, 128>>>(sf, sh, sl);
    // mix1[b] = P1[b] @ X[b]   (B = X^T, K-major over m) -- 3-pass (R15 showed
    // 2-pass here costs 1.44e-3: over budget)
    gemm_hmma<false, false, false, true, false><<<dim3(4, 4, 256), 256, GEMM_DYN_SMEM>>>(
        sh, sl, 512, LDb, xth, xtl, 512, LDb,
        nullptr, nullptr, nullptr, nullptr, mh, ml, nullptr, 512, LDb, 512);
    // h = tanh(mix1 @ Wout1[:, :512]^T + q1 @ Wout1[:, 512:]^T) -> overwrite X slots
    gemm_hmma<true, true, false, true, false><<<dim3(4, 1024, 1), 256, GEMM_DYN_SMEM>>>(
        mh, ml, 512, 0, wo1h, wo1l, 1024, 0,
        qh, ql, wo1h + 512, wo1l + 512, xh, xl, nullptr, 512, 0, 512);

    // ---- block 2 (2-pass GEMMs: mean-pool over L suppresses their error) ----
    // q2 = h @ Win2^T; epilogue emits fp32 column-sum partials (qbar4) and
    // writes only the hi part (ql unused by 2-pass S2).
    gemm_hmma<false, false, false, false, true><<<dim3(4, 1024, 1), 256, GEMM_DYN_SMEM>>>(
        xh, xl, 512, 0, w2h, w2l, 512, 0,
        nullptr, nullptr, nullptr, nullptr, qh, nullptr, qbar4, 512, 0, 512);
    // S2[b] = q2[b] @ h[b]^T  (fp32 out)
    gemm_hmma<false, false, true, false, false><<<dim3(4, 4, 256), 256, GEMM_DYN_SMEM>>>(
        qh, ql, 512, LDb, xh, xl, 512, LDb,
        nullptr, nullptr, nullptr, nullptr, nullptr, nullptr, sf, 512, LDb, 512);

    // ---- fused tail: softmax(S2) column means without materializing P2 ----
    softmax_colmean_kernel<<<dim3(4, 256), 256>>>(sf, pbar4);
    mixfinal_kernel<<<BATCH, 512>>>(pbar4, qbar4, xh, xl, Wout2, out);
}

// round 17
// speedup vs baseline: 1.4698x; 1.2884x over previous
#include <cuda_runtime.h>
#include <cuda_fp16.h>
#include <math.h>
#include <stdint.h>

#define BATCH 256
#define SEQ   512
#define DIM   512

static const long NEL = (long)BATCH * SEQ * DIM;  // 67108864

// ---------------------------------------------------------------------------
// Scratch: __device__ globals (allocation-free rule). fp16 hi/lo splits.
// ---------------------------------------------------------------------------
static __device__ __half g_xh[67108864], g_xl[67108864];   // X / later h
static __device__ __half g_xth[67108864], g_xtl[67108864]; // X^T (block 1)
static __device__ __half g_qh[67108864], g_ql[67108864];   // q1 / q2
static __device__ __half g_sh[67108864], g_sl[67108864];   // P1 hi/lo
static __device__ __half g_mh[67108864], g_ml[67108864];   // mix1
static __device__ float g_sf[67108864];                    // scores fp32
static __device__ __half g_w1h[262144], g_w1l[262144];
static __device__ __half g_wo1h[524288], g_wo1l[524288];
static __device__ __half g_w2h[262144], g_w2l[262144];
static __device__ float g_pbar4[524288];   // [4][256][512] P2 col-sum partials
static __device__ float g_qbar4[524288];   // [4][256][512] q2 col-sum partials

// ---------------------------------------------------------------------------
// PTX helpers (sm_80+ baseline: cp.async / ldmatrix / mma.sync fp16)
// ---------------------------------------------------------------------------
__device__ __forceinline__ void cp_async16(uint32_t s, const void* g) {
    asm volatile("cp.async.cg.shared.global [%0], [%1], 16;"
                 :: "r"(s), "l"(__cvta_generic_to_global(g)) : "memory");
}

__device__ __forceinline__ void ldsm_x4(uint32_t addr, uint32_t& r0, uint32_t& r1,
                                        uint32_t& r2, uint32_t& r3) {
    asm volatile("ldmatrix.sync.aligned.m8n8.x4.shared.b16 {%0,%1,%2,%3}, [%4];"
                 : "=r"(r0), "=r"(r1), "=r"(r2), "=r"(r3) : "r"(addr));
}

__device__ __forceinline__ void mma16816(float* c, const uint32_t* a, const uint32_t* b) {
    asm volatile("mma.sync.aligned.m16n8k16.row.col.f32.f16.f16.f32 "
                 "{%0,%1,%2,%3}, {%4,%5,%6,%7}, {%8,%9}, {%0,%1,%2,%3};"
                 : "+f"(c[0]), "+f"(c[1]), "+f"(c[2]), "+f"(c[3])
                 : "r"(a[0]), "r"(a[1]), "r"(a[2]), "r"(a[3]), "r"(b[0]), "r"(b[1]));
}

// ---------------------------------------------------------------------------
// Split-fp16 HMMA GEMM, 2-pass everywhere:
//   C = AH*BH + AH*BL   (dropped AL*B term ~2^-11 relative -- fp16 hi residual
//   is 8x smaller than bf16's; calibrated error fits the 1e-3 budget).
//   A-lo is never read -> load only AH, BH, BL (3 tiles).
//   Block tile 128x128, BK=32, 256 thr (2x4 warps, 64x32 warp tile).
//   SMEM rows 128B (B: [hi 64B | lo 64B]; A: hi in first 64B), XOR swizzle.
//   3-stage cp.async pipeline (wait_group 1), one __syncthreads per chunk.
//   QSUM: epilogue also emits per-block fp32 column sums; skips cL write.
// ---------------------------------------------------------------------------
#define BK      32
#define TILE_B  (128 * 128)           // 16384 B per operand slot
#define STAGE_B (2 * TILE_B)          // A, B
#define NSTAGE  3
#define GEMM_DYN_SMEM (NSTAGE * STAGE_B)   // 98304 B

// granule g (16B) at row r -> g ^ (r&7) within the 128B row
__device__ __forceinline__ void load_chunk(uint32_t sbase,
    const __half* pAH, const __half* pBH, const __half* pBL,
    long rowA, long colB, int lda, int ldb, int k0, int tid)
{
#pragma unroll
    for (int i = 0; i < 6; ++i) {
        int seg = tid + i * 256;            // 0..1535 16B segments
        int u   = seg >> 9;                 // 0=AH, 1=BH, 2=BL
        int r   = (seg >> 2) & 127;         // row 0..127
        int c   = seg & 3;                  // 16B col chunk 0..3
        const __half* src = (u == 0) ? pAH : ((u == 1) ? pBH : pBL);
        uint32_t tb = (u == 0) ? 0u : (uint32_t)TILE_B;
        int g = (u == 2) ? (c + 4) : c;     // B-lo lives in bytes 64..127
        long row0 = (u == 0) ? rowA : colB;
        int  ld   = (u == 0) ? lda  : ldb;
        cp_async16(sbase + tb + (uint32_t)(r * 128 + ((g ^ (r & 7)) * 16)),
                   src + (row0 + r) * (long)ld + k0 + c * 8);
    }
    asm volatile("cp.async.commit_group;" ::: "memory");
}

template<bool DUAL, bool TANH, bool OUTF32, bool QSUM>
__global__ void __launch_bounds__(256, 2)
gemm_hmma(const __half* __restrict__ aH, int lda, long sA,
          const __half* __restrict__ bH, const __half* __restrict__ bL,
          int ldb, long sB,
          const __half* __restrict__ a2H,
          const __half* __restrict__ b2H, const __half* __restrict__ b2L,
          __half* __restrict__ cH, __half* __restrict__ cL,
          float* __restrict__ cF,
          int ldc, long sC, int K)
{
    extern __shared__ char smem_raw[];
    const uint32_t smem = (uint32_t)__cvta_generic_to_shared(smem_raw);
    __shared__ float cs[2][128];   // QSUM cross-warp column partials

    const int tid  = threadIdx.x;
    const int lane = tid & 31;
    const int wid  = tid >> 5;
    const int wm   = wid & 1;       // 2 m-groups of 64
    const int wn   = wid >> 1;      // 4 n-groups of 32
    const int bz   = blockIdx.z;
    const long rowA = (long)blockIdx.y * 128;
    const long colB = (long)blockIdx.x * 128;

    float acc[4][4][4];
#pragma unroll
    for (int i = 0; i < 4; ++i)
#pragma unroll
        for (int j = 0; j < 4; ++j)
#pragma unroll
            for (int k = 0; k < 4; ++k) acc[i][j][k] = 0.f;

    const int npc    = K / BK;                 // chunks per pair
    const int nchunk = (DUAL ? 2 : 1) * npc;

    const __half* AH0 = aH + bz * sA;
    const __half* BH0 = bH + bz * sB;
    const __half* BL0 = bL + bz * sB;
    const __half* AH1 = DUAL ? a2H + bz * sA : nullptr;
    const __half* BH1 = DUAL ? b2H + bz * sB : nullptr;
    const __half* BL1 = DUAL ? b2L + bz * sB : nullptr;

    // Per-thread fragment address constants (swizzle folded in; row&7 == lane&7).
    const uint32_t aRowB = (uint32_t)((wm * 64 + (lane & 15)) * 128);
    const uint32_t bRowB = (uint32_t)((wn * 32 + ((lane >> 4) << 3) + (lane & 7)) * 128);
    uint32_t gA16[2], gB16[2];
#pragma unroll
    for (int ks = 0; ks < 2; ++ks) {
        gA16[ks] = (uint32_t)(((ks * 2 + (lane >> 4)) ^ (lane & 7)) * 16);
        gB16[ks] = (uint32_t)(((ks * 2 + ((lane >> 3) & 1)) ^ (lane & 7)) * 16);
    }

    // prologue: chunks 0,1 -> stages 0,1 (all GEMMs here have nchunk >= 16)
    load_chunk(smem,           AH0, BH0, BL0, rowA, colB, lda, ldb, 0,  tid);
    load_chunk(smem + STAGE_B, AH0, BH0, BL0, rowA, colB, lda, ldb, BK, tid);

    for (int c = 0; c < nchunk; ++c) {
        if (c + 1 < nchunk)
            asm volatile("cp.async.wait_group 1;" ::: "memory");
        else
            asm volatile("cp.async.wait_group 0;" ::: "memory");
        __syncthreads();   // stage c%3 ready; all warps done with stage (c-1)%3

        if (c + 2 < nchunk) {
            int cn = c + 2;
            int p  = cn / npc;
            int k0 = (cn % npc) * BK;
            uint32_t dst = smem + (uint32_t)((cn % NSTAGE) * STAGE_B);
            if (!DUAL || p == 0)
                load_chunk(dst, AH0, BH0, BL0, rowA, colB, lda, ldb, k0, tid);
            else
                load_chunk(dst, AH1, BH1, BL1, rowA, colB, lda, ldb, k0, tid);
        }

        const uint32_t sA_ = smem + (uint32_t)((c % NSTAGE) * STAGE_B);
        const uint32_t sB_ = sA_ + TILE_B;

#pragma unroll
        for (int ks = 0; ks < 2; ++ks) {
            uint32_t bhf[4][2], blf[4][2];
#pragma unroll
            for (int np = 0; np < 2; ++np) {
                uint32_t boff = bRowB + (uint32_t)(np * 16 * 128);
                ldsm_x4(sB_ + boff + gB16[ks], bhf[2 * np][0], bhf[2 * np][1],
                                               bhf[2 * np + 1][0], bhf[2 * np + 1][1]);
                ldsm_x4(sB_ + (boff + gB16[ks] ^ 64u), blf[2 * np][0], blf[2 * np][1],
                                               blf[2 * np + 1][0], blf[2 * np + 1][1]);
            }
#pragma unroll
            for (int mf = 0; mf < 4; ++mf) {
                uint32_t aoff = aRowB + (uint32_t)(mf * 16 * 128);
                uint32_t ahf[4];
                ldsm_x4(sA_ + aoff + gA16[ks], ahf[0], ahf[1], ahf[2], ahf[3]);
#pragma unroll
                for (int nf = 0; nf < 4; ++nf) {
                    mma16816(acc[mf][nf], ahf, bhf[nf]);  // hi*hi
                    mma16816(acc[mf][nf], ahf, blf[nf]);  // hi*lo
                }
            }
        }
    }

    // Epilogue: c0,c1 -> (row=rq, col=cq..cq+1); c2,c3 -> row+8.
    const int rq = lane >> 2, cq = (lane & 3) * 2;

#pragma unroll
    for (int mf = 0; mf < 4; ++mf) {
#pragma unroll
        for (int nf = 0; nf < 4; ++nf) {
            long col = colB + wn * 32 + nf * 8 + cq;
#pragma unroll
            for (int half = 0; half < 2; ++half) {
                long row = rowA + wm * 64 + mf * 16 + rq + half * 8;
                float v0 = acc[mf][nf][half * 2 + 0];
                float v1 = acc[mf][nf][half * 2 + 1];
                if (OUTF32) {
                    float* CF = cF + (long)bz * sC;
                    *(float2*)(CF + row * (long)ldc + col) = make_float2(v0, v1);
                } else if (QSUM) {
                    // hi only; lo is dead (2-pass S2 never reads A-lo)
                    __half2 hp = __floats2half2_rn(v0, v1);
                    *(__half2*)(cH + row * (long)ldc + col) = hp;
                } else {
                    if (TANH) { v0 = tanhf(v0); v1 = tanhf(v1); }
                    __half h0 = __float2half_rn(v0);
                    __half h1 = __float2half_rn(v1);
                    __half l0 = __float2half_rn(v0 - __half2float(h0));
                    __half l1 = __float2half_rn(v1 - __half2float(h1));
                    __half2 hp = __halves2half2(h0, h1);
                    __half2 lp = __halves2half2(l0, l1);
                    __half* CH = cH + (long)bz * sC;
                    __half* CL = cL + (long)bz * sC;
                    *(__half2*)(CH + row * (long)ldc + col) = hp;
                    *(__half2*)(CL + row * (long)ldc + col) = lp;
                }
            }
        }
    }

    if (QSUM) {
        // Per-block fp32 column sums (deterministic, no atomics).
        float cl[4][2];
#pragma unroll
        for (int nf = 0; nf < 4; ++nf)
#pragma unroll
            for (int j = 0; j < 2; ++j) {
                float s = 0.f;
#pragma unroll
                for (int mf = 0; mf < 4; ++mf)
                    s += acc[mf][nf][j] + acc[mf][nf][2 + j];
                cl[nf][j] = s;
            }
#pragma unroll
        for (int off = 4; off <= 16; off <<= 1)
#pragma unroll
            for (int nf = 0; nf < 4; ++nf)
#pragma unroll
                for (int j = 0; j < 2; ++j)
                    cl[nf][j] += __shfl_xor_sync(0xffffffffu, cl[nf][j], off);
        if (lane < 4) {
#pragma unroll
            for (int nf = 0; nf < 4; ++nf)
#pragma unroll
                for (int j = 0; j < 2; ++j)
                    cs[wm][wn * 32 + nf * 8 + lane * 2 + j] = cl[nf][j];
        }
        __syncthreads();
        if (tid < 128) {
            const int sub = (int)(blockIdx.y & 3);
            const int b   = (int)(blockIdx.y >> 2);
            cF[((long)sub * 256 + b) * 512 + colB + tid] = cs[0][tid] + cs[1][tid];
        }
    }
}

// ---------------------------------------------------------------------------
// fp32 -> (hi, lo) fp16 split helpers
// ---------------------------------------------------------------------------
__device__ __forceinline__ void split4(float4 v, uint2& uh, uint2& ul)
{
    float f[4] = {v.x, v.y, v.z, v.w};
    __half h[4], l[4];
#pragma unroll
    for (int j = 0; j < 4; ++j) {
        h[j] = __float2half_rn(f[j]);
        l[j] = __float2half_rn(f[j] - __half2float(h[j]));
    }
    __half2 h01 = __halves2half2(h[0], h[1]), h23 = __halves2half2(h[2], h[3]);
    __half2 l01 = __halves2half2(l[0], l[1]), l23 = __halves2half2(l[2], l[3]);
    uh.x = *(uint32_t*)&h01; uh.y = *(uint32_t*)&h23;
    ul.x = *(uint32_t*)&l01; ul.y = *(uint32_t*)&l23;
}

__device__ __forceinline__ void split1(float f, __half& h, __half& l)
{
    h = __float2half_rn(f);
    l = __float2half_rn(f - __half2float(h));
}

// Fused weight split: W1 (65536 f4) | Wout1 (131072 f4) | W2 (65536 f4)
__global__ void __launch_bounds__(256)
wsplit_kernel(const float4* __restrict__ w1, const float4* __restrict__ wo1,
              const float4* __restrict__ w2,
              uint2* __restrict__ w1h, uint2* __restrict__ w1l,
              uint2* __restrict__ wo1h, uint2* __restrict__ wo1l,
              uint2* __restrict__ w2h, uint2* __restrict__ w2l)
{
    long i = (long)blockIdx.x * blockDim.x + threadIdx.x;
    const float4* src; uint2 *dh, *dl; long j;
    if (i < 65536)       { src = w1;  dh = w1h;  dl = w1l;  j = i; }
    else if (i < 196608) { src = wo1; dh = wo1h; dl = wo1l; j = i - 65536; }
    else                 { src = w2;  dh = w2h;  dl = w2l;  j = i - 196608; }
    uint2 uh, ul;
    split4(src[j], uh, ul);
    dh[j] = uh; dl[j] = ul;
}

// ---------------------------------------------------------------------------
// Fused X split + transpose: reads X fp32 once, writes xh/xl (row-major) and
// xth/xtl (transposed). 32x32 tiles, block (32,8), grid (16,16,256).
// ---------------------------------------------------------------------------
__global__ void __launch_bounds__(256)
splitT_kernel(const float* __restrict__ X,
              __half* __restrict__ xh, __half* __restrict__ xl,
              __half* __restrict__ xth, __half* __restrict__ xtl)
{
    __shared__ float tile[32][33];
    const long base = (long)blockIdx.z * 262144;
    const int tx = threadIdx.x, ty = threadIdx.y;
    const int x = blockIdx.x * 32 + tx;
    const int y0 = blockIdx.y * 32;

#pragma unroll
    for (int j = 0; j < 32; j += 8) {
        long idx = base + (long)(y0 + ty + j) * 512 + x;
        float v = X[idx];
        tile[ty + j][tx] = v;
        __half h, l;
        split1(v, h, l);
        xh[idx] = h; xl[idx] = l;
    }
    __syncthreads();

    const int xo = blockIdx.y * 32 + tx;
    const int yo0 = blockIdx.x * 32;
#pragma unroll
    for (int j = 0; j < 32; j += 8) {
        long idx = base + (long)(yo0 + ty + j) * 512 + xo;
        float v = tile[tx][ty + j];
        __half h, l;
        split1(v, h, l);
        xth[idx] = h; xtl[idx] = l;
    }
}

// ---------------------------------------------------------------------------
// Row softmax over 512: fp32 in, hi/lo fp16 out (block 1 -- P feeds a GEMM).
// ---------------------------------------------------------------------------
__global__ void __launch_bounds__(128)
softmax512_f32(const float* __restrict__ S,
               __half* __restrict__ PH, __half* __restrict__ PL)
{
    __shared__ float redm[4], reds[4];
    const long row = blockIdx.x;
    const int t = threadIdx.x;

    float4 vv = ((const float4*)(S + row * 512))[t];
    float v[4] = {vv.x, vv.y, vv.z, vv.w};

    float m = fmaxf(fmaxf(v[0], v[1]), fmaxf(v[2], v[3]));
#pragma unroll
    for (int o = 16; o; o >>= 1) m = fmaxf(m, __shfl_xor_sync(0xffffffffu, m, o));
    if ((t & 31) == 0) redm[t >> 5] = m;
    __syncthreads();
    m = fmaxf(fmaxf(redm[0], redm[1]), fmaxf(redm[2], redm[3]));

    float s = 0.f;
#pragma unroll
    for (int j = 0; j < 4; ++j) { v[j] = __expf(v[j] - m); s += v[j]; }
#pragma unroll
    for (int o = 16; o; o >>= 1) s += __shfl_xor_sync(0xffffffffu, s, o);
    if ((t & 31) == 0) reds[t >> 5] = s;
    __syncthreads();
    s = reds[0] + reds[1] + reds[2] + reds[3];
    float r = 1.0f / s;

    float4 w = make_float4(v[0] * r, v[1] * r, v[2] * r, v[3] * r);
    uint2 uh, ul;
    split4(w, uh, ul);
    ((uint2*)(PH + row * 512))[t] = uh;
    ((uint2*)(PL + row * 512))[t] = ul;
}

// ---------------------------------------------------------------------------
// Block-2 fused softmax + column-sum (P2 never materialized).
// Grid (4, 256): block (rg, b) handles rows [rg*128, rg*128+128) of batch b.
// ---------------------------------------------------------------------------
__global__ void __launch_bounds__(256)
softmax_colmean_kernel(const float* __restrict__ S, float* __restrict__ pbar4)
{
    __shared__ float part[8][512];
    const int b = blockIdx.y, rg = blockIdx.x;
    const int wid = threadIdx.x >> 5, lane = threadIdx.x & 31;

    const float* Sb = S + (long)b * 262144 + (long)(rg * 128 + wid * 16) * 512;

    float csum[16];
#pragma unroll
    for (int j = 0; j < 16; ++j) csum[j] = 0.f;

    for (int r = 0; r < 16; ++r) {
        const float* row = Sb + (long)r * 512;
        float v[16];
#pragma unroll
        for (int j = 0; j < 16; ++j) v[j] = row[lane + 32 * j];
        float m = v[0];
#pragma unroll
        for (int j = 1; j < 16; ++j) m = fmaxf(m, v[j]);
#pragma unroll
        for (int o = 16; o; o >>= 1) m = fmaxf(m, __shfl_xor_sync(0xffffffffu, m, o));
        float s = 0.f;
#pragma unroll
        for (int j = 0; j < 16; ++j) { v[j] = __expf(v[j] - m); s += v[j]; }
#pragma unroll
        for (int o = 16; o; o >>= 1) s += __shfl_xor_sync(0xffffffffu, s, o);
        float inv = 1.0f / s;
#pragma unroll
        for (int j = 0; j < 16; ++j) csum[j] += v[j] * inv;
    }

#pragma unroll
    for (int j = 0; j < 16; ++j) part[wid][lane + 32 * j] = csum[j];
    __syncthreads();

#pragma unroll
    for (int cc = 0; cc < 2; ++cc) {
        int col = threadIdx.x + cc * 256;
        float s = 0.f;
#pragma unroll
        for (int w = 0; w < 8; ++w) s += part[w][col];
        pbar4[((long)rg * 256 + b) * 512 + col] = s;
    }
}

// ---------------------------------------------------------------------------
// Fused mixbar + final projection. One block per batch b (512 thr).
// ---------------------------------------------------------------------------
__global__ void __launch_bounds__(512)
mixfinal_kernel(const float* __restrict__ pbar4, const float* __restrict__ qbar4,
                const __half* __restrict__ hh, const __half* __restrict__ hl,
                const float* __restrict__ W, float* __restrict__ out)
{
    __shared__ float pb[512], mb[512], qb[512];
    const int b = blockIdx.x, d = threadIdx.x;
    float p = 0.f, q = 0.f;
#pragma unroll
    for (int rg = 0; rg < 4; ++rg) {
        p += pbar4[((long)rg * 256 + b) * 512 + d];
        q += qbar4[((long)rg * 256 + b) * 512 + d];
    }
    pb[d] = p * (1.0f / 512.0f);
    qb[d] = q * (1.0f / 512.0f);
    __syncthreads();

    const long base = (long)b * 262144 + d;
    float s = 0.f;
#pragma unroll 4
    for (int m = 0; m < 512; ++m) {
        long off = base + (long)m * 512;
        s += pb[m] * (__half2float(hh[off]) + __half2float(hl[off]));
    }
    mb[d] = s;
    __syncthreads();

    const float4* w4 = (const float4*)(W + (long)d * 1024);
    float o = 0.f;
#pragma unroll 4
    for (int c4 = 0; c4 < 128; ++c4) {
        float4 w = w4[c4];
        int c = c4 * 4;
        o += mb[c] * w.x + mb[c + 1] * w.y + mb[c + 2] * w.z + mb[c + 3] * w.w;
    }
#pragma unroll 4
    for (int c4 = 128; c4 < 256; ++c4) {
        float4 w = w4[c4];
        int c = c4 * 4 - 512;
        o += qb[c] * w.x + qb[c + 1] * w.y + qb[c + 2] * w.z + qb[c + 3] * w.w;
    }
    out[b * 512 + d] = o;
}

// ---------------------------------------------------------------------------

extern "C" void kernel_launch(void* const* d_in, const int* in_sizes, int n_in,
                              void* d_out, int out_size)
{
    const float* x     = (const float*)d_in[0];
    const float* Win1  = (const float*)d_in[1];
    const float* Wout1 = (const float*)d_in[2];
    const float* Win2  = (const float*)d_in[3];
    const float* Wout2 = (const float*)d_in[4];
    float* out = (float*)d_out;

    __half *xh, *xl, *xth, *xtl, *qh, *ql, *sh, *sl, *mh, *ml;
    __half *w1h, *w1l, *wo1h, *wo1l, *w2h, *w2l;
    float *sf, *pbar4, *qbar4;
    cudaGetSymbolAddress((void**)&xh,  g_xh);   cudaGetSymbolAddress((void**)&xl,  g_xl);
    cudaGetSymbolAddress((void**)&xth, g_xth);  cudaGetSymbolAddress((void**)&xtl, g_xtl);
    cudaGetSymbolAddress((void**)&qh,  g_qh);   cudaGetSymbolAddress((void**)&ql,  g_ql);
    cudaGetSymbolAddress((void**)&sh,  g_sh);   cudaGetSymbolAddress((void**)&sl,  g_sl);
    cudaGetSymbolAddress((void**)&mh,  g_mh);   cudaGetSymbolAddress((void**)&ml,  g_ml);
    cudaGetSymbolAddress((void**)&sf,  g_sf);
    cudaGetSymbolAddress((void**)&w1h, g_w1h);  cudaGetSymbolAddress((void**)&w1l, g_w1l);
    cudaGetSymbolAddress((void**)&wo1h,g_wo1h); cudaGetSymbolAddress((void**)&wo1l,g_wo1l);
    cudaGetSymbolAddress((void**)&w2h, g_w2h);  cudaGetSymbolAddress((void**)&w2l, g_w2l);
    cudaGetSymbolAddress((void**)&pbar4, g_pbar4);
    cudaGetSymbolAddress((void**)&qbar4, g_qbar4);

    cudaFuncSetAttribute(gemm_hmma<false, false, false, false>,
                         cudaFuncAttributeMaxDynamicSharedMemorySize, GEMM_DYN_SMEM);
    cudaFuncSetAttribute(gemm_hmma<false, false, true, false>,
                         cudaFuncAttributeMaxDynamicSharedMemorySize, GEMM_DYN_SMEM);
    cudaFuncSetAttribute(gemm_hmma<true, true, false, false>,
                         cudaFuncAttributeMaxDynamicSharedMemorySize, GEMM_DYN_SMEM);
    cudaFuncSetAttribute(gemm_hmma<false, false, false, true>,
                         cudaFuncAttributeMaxDynamicSharedMemorySize, GEMM_DYN_SMEM);

    const int  M_FLAT = BATCH * SEQ;     // 131072
    const long LDb = 262144;

    // ---- splits (X split fused with transpose) ----
    wsplit_kernel<<<262144 / 256, 256>>>(
        (const float4*)Win1, (const float4*)Wout1, (const float4*)Win2,
        (uint2*)w1h, (uint2*)w1l, (uint2*)wo1h, (uint2*)wo1l, (uint2*)w2h, (uint2*)w2l);
    splitT_kernel<<<dim3(16, 16, 256), dim3(32, 8)>>>(x, xh, xl, xth, xtl);

    // ---- block 1 ----
    // q1 = X @ Win1^T
    gemm_hmma<false, false, false, false><<<dim3(4, 1024, 1), 256, GEMM_DYN_SMEM>>>(
        xh, 512, 0, w1h, w1l, 512, 0,
        nullptr, nullptr, nullptr, qh, ql, nullptr, 512, 0, 512);
    // S1[b] = q1[b] @ X[b]^T  (fp32 out)
    gemm_hmma<false, false, true, false><<<dim3(4, 4, 256), 256, GEMM_DYN_SMEM>>>(
        qh, 512, LDb, xh, xl, 512, LDb,
        nullptr, nullptr, nullptr, nullptr, nullptr, sf, 512, LDb, 512);
    softmax512_f32<<<M_FLAT, 128>>>(sf, sh, sl);
    // mix1[b] = P1[b] @ X[b]   (B = X^T, K-major over m)
    gemm_hmma<false, false, false, false><<<dim3(4, 4, 256), 256, GEMM_DYN_SMEM>>>(
        sh, 512, LDb, xth, xtl, 512, LDb,
        nullptr, nullptr, nullptr, mh, ml, nullptr, 512, LDb, 512);
    // h = tanh(mix1 @ Wout1[:, :512]^T + q1 @ Wout1[:, 512:]^T) -> overwrite X slots
    gemm_hmma<true, true, false, false><<<dim3(4, 1024, 1), 256, GEMM_DYN_SMEM>>>(
        mh, 512, 0, wo1h, wo1l, 1024, 0,
        qh, wo1h + 512, wo1l + 512, xh, xl, nullptr, 512, 0, 512);

    // ---- block 2 ----
    // q2 = h @ Win2^T; epilogue emits fp32 column-sum partials (qbar4),
    // writes hi only (ql unused by 2-pass S2).
    gemm_hmma<false, false, false, true><<<dim3(4, 1024, 1), 256, GEMM_DYN_SMEM>>>(
        xh, 512, 0, w2h, w2l, 512, 0,
        nullptr, nullptr, nullptr, qh, nullptr, qbar4, 512, 0, 512);
    // S2[b] = q2[b] @ h[b]^T  (fp32 out)
    gemm_hmma<false, false, true, false><<<dim3(4, 4, 256), 256, GEMM_DYN_SMEM>>>(
        qh, 512, LDb, xh, xl, 512, LDb,
        nullptr, nullptr, nullptr, nullptr, nullptr, sf, 512, LDb, 512);

    // ---- fused tail: softmax(S2) column means without materializing P2 ----
    softmax_colmean_kernel<<<dim3(4, 256), 256>>>(sf, pbar4);
    mixfinal_kernel<<<BATCH, 512>>>(pbar4, qbar4, xh, xl, Wout2, out);
}